// round 1
// baseline (speedup 1.0000x reference)
#include <cuda_runtime.h>
#include <math.h>
#include <stdint.h>

// Problem dims
#define BB   4
#define SS   1024
#define DD   768
#define HH   12
#define VV   32000
#define LL   2
#define DK   64
#define DFF  3072
#define MM   (BB*SS)          // 4096 rows

#define LOGITS_ELEMS ((size_t)BB*SS*VV)           // 131072000
#define AMAP_ELEMS   ((size_t)BB*HH*SS*SS)        // 50331648 per layer

// ---------------- scratch (no allocations allowed) ----------------
__device__ float g_h [MM*DD];
__device__ float g_q [MM*DD];
__device__ float g_k [MM*DD];
__device__ float g_v [MM*DD];
__device__ float g_t [MM*DD];
__device__ float g_ff[MM*DFF];

// ---------------- embedding: h = emb[x]*sqrt(D) + pe[:S] ----------------
__global__ void embed_kernel(const int* __restrict__ x,
                             const float* __restrict__ emb,
                             const float* __restrict__ pe)
{
    int i = blockIdx.x * 256 + threadIdx.x;
    if (i >= MM*DD) return;
    int row = i / DD;
    int d   = i - row*DD;
    int s   = row & (SS-1);
    int tok = x[row];
    g_h[i] = emb[(size_t)tok*DD + d] * 27.712812921102035f + pe[(size_t)s*DD + d];
}

// ---------------- generic SGEMM: C[M,N] = A[M,K] @ W[K,N] + bias, opt relu ----
// BM=BN=64, BK=16, 16x16 threads, 4x4 per thread. All dims multiple of 64/16.
__global__ void sgemm_kernel(const float* __restrict__ A,
                             const float* __restrict__ W,
                             const float* __restrict__ bias,
                             float* __restrict__ C,
                             int K, int N, int relu)
{
    __shared__ float As[16][64];   // [k][m]
    __shared__ float Bs[16][64];   // [k][n]
    const int tx = threadIdx.x, ty = threadIdx.y;
    const int tid = ty*16 + tx;
    const int row0 = blockIdx.y * 64;
    const int col0 = blockIdx.x * 64;

    float c[4][4] = {};

    for (int k0 = 0; k0 < K; k0 += 16) {
        // A tile: 64x16. thread -> m=tid/4, 4 consecutive k as float4
        {
            int m  = tid >> 2;
            int kq = (tid & 3) * 4;
            float4 a4 = *(const float4*)(A + (size_t)(row0+m)*K + k0 + kq);
            As[kq+0][m] = a4.x; As[kq+1][m] = a4.y;
            As[kq+2][m] = a4.z; As[kq+3][m] = a4.w;
        }
        // B tile: 16x64. thread -> k=tid/16, 4 consecutive n as float4
        {
            int kb = tid >> 4;
            int nq = (tid & 15) * 4;
            *(float4*)(&Bs[kb][nq]) = *(const float4*)(W + (size_t)(k0+kb)*N + col0 + nq);
        }
        __syncthreads();

        #pragma unroll
        for (int kk = 0; kk < 16; kk++) {
            float a[4], b[4];
            #pragma unroll
            for (int i = 0; i < 4; i++) a[i] = As[kk][ty*4+i];
            #pragma unroll
            for (int j = 0; j < 4; j++) b[j] = Bs[kk][tx*4+j];
            #pragma unroll
            for (int i = 0; i < 4; i++)
                #pragma unroll
                for (int j = 0; j < 4; j++)
                    c[i][j] += a[i]*b[j];
        }
        __syncthreads();
    }

    #pragma unroll
    for (int i = 0; i < 4; i++) {
        int r = row0 + ty*4 + i;
        #pragma unroll
        for (int j = 0; j < 4; j++) {
            int cc = col0 + tx*4 + j;
            float v = c[i][j] + bias[cc];
            if (relu) v = fmaxf(v, 0.0f);
            C[(size_t)r*N + cc] = v;
        }
    }
}

// ---------------- attention scores + softmax, writes attn map --------------
// grid (S, B*H), 256 threads
__global__ void attn_scores_kernel(const float* __restrict__ Q,
                                   const float* __restrict__ Km,
                                   float* __restrict__ amap)
{
    const int qpos = blockIdx.x;
    const int bh   = blockIdx.y;          // b*H + h
    const int b    = bh / HH;
    const int hh   = bh - b*HH;
    const int tid  = threadIdx.x;

    __shared__ float qs[DK];
    __shared__ float sc[SS];
    __shared__ float red[256];

    if (tid < DK)
        qs[tid] = Q[((size_t)(b*SS + qpos))*DD + hh*DK + tid] * 0.125f; // 1/sqrt(64)
    __syncthreads();

    for (int k = tid; k < SS; k += 256) {
        float dot = -1e30f;
        if (k <= qpos) {
            const float4* kr = (const float4*)(Km + ((size_t)(b*SS + k))*DD + hh*DK);
            const float4* qv = (const float4*)qs;
            dot = 0.0f;
            #pragma unroll
            for (int i = 0; i < 16; i++) {
                float4 kv = kr[i], q4 = qv[i];
                dot += q4.x*kv.x + q4.y*kv.y + q4.z*kv.z + q4.w*kv.w;
            }
        }
        sc[k] = dot;
    }
    __syncthreads();

    // max
    float m = -1e30f;
    for (int k = tid; k < SS; k += 256) m = fmaxf(m, sc[k]);
    red[tid] = m; __syncthreads();
    for (int s = 128; s > 0; s >>= 1) {
        if (tid < s) red[tid] = fmaxf(red[tid], red[tid+s]);
        __syncthreads();
    }
    m = red[0];
    __syncthreads();

    // exp + sum
    float sum = 0.0f;
    for (int k = tid; k < SS; k += 256) {
        float e = (k <= qpos) ? __expf(sc[k] - m) : 0.0f;
        sc[k] = e;
        sum += e;
    }
    red[tid] = sum; __syncthreads();
    for (int s = 128; s > 0; s >>= 1) {
        if (tid < s) red[tid] += red[tid+s];
        __syncthreads();
    }
    float inv = 1.0f / red[0];

    float* arow = amap + ((size_t)bh*SS + qpos)*SS;
    for (int k = tid; k < SS; k += 256) arow[k] = sc[k] * inv;
}

// ---------------- o = a @ v, written back in (B,S,D) layout ----------------
// grid (S, B*H), 64 threads (one per dk)
__global__ void attn_o_kernel(const float* __restrict__ amap,
                              const float* __restrict__ Vm,
                              float* __restrict__ O)
{
    const int qpos = blockIdx.x;
    const int bh   = blockIdx.y;
    const int b    = bh / HH;
    const int hh   = bh - b*HH;
    const int d    = threadIdx.x;

    const float* arow = amap + ((size_t)bh*SS + qpos)*SS;
    const float* vb   = Vm + ((size_t)(b*SS))*DD + hh*DK + d;

    float acc = 0.0f;
    int kend = qpos + 1;
    #pragma unroll 4
    for (int k = 0; k < kend; k++)
        acc += arow[k] * vb[(size_t)k*DD];

    O[((size_t)(b*SS + qpos))*DD + hh*DK + d] = acc;
}

// ---------------- residual add + layernorm --------------------------------
// grid MM, 256 threads. out = LN(res + x) * g + be. out may alias res.
__global__ void add_ln_kernel(const float* __restrict__ res,
                              const float* __restrict__ x,
                              const float* __restrict__ g,
                              const float* __restrict__ be,
                              float* __restrict__ out)
{
    const int row = blockIdx.x;
    const int tid = threadIdx.x;
    __shared__ float buf[DD];
    __shared__ float red[256];

    float s = 0.0f;
    for (int d = tid; d < DD; d += 256) {
        float v = res[(size_t)row*DD + d] + x[(size_t)row*DD + d];
        buf[d] = v;
        s += v;
    }
    red[tid] = s; __syncthreads();
    for (int t = 128; t > 0; t >>= 1) {
        if (tid < t) red[tid] += red[tid+t];
        __syncthreads();
    }
    float mean = red[0] * (1.0f/DD);
    __syncthreads();

    float vs = 0.0f;
    for (int d = tid; d < DD; d += 256) {
        float dv = buf[d] - mean;
        vs += dv*dv;
    }
    red[tid] = vs; __syncthreads();
    for (int t = 128; t > 0; t >>= 1) {
        if (tid < t) red[tid] += red[tid+t];
        __syncthreads();
    }
    float rstd = rsqrtf(red[0] * (1.0f/DD) + 1e-5f);

    for (int d = tid; d < DD; d += 256)
        out[(size_t)row*DD + d] = (buf[d] - mean)*rstd*g[d] + be[d];
}

// ---------------------------------------------------------------------------
extern "C" void kernel_launch(void* const* d_in, const int* in_sizes, int n_in,
                              void* d_out, int out_size)
{
    (void)in_sizes; (void)n_in; (void)out_size;

    const int*   x    = (const int*)  d_in[0];
    // d_in[1] = mask (tril) — causal handled analytically
    const float* emb  = (const float*)d_in[2];
    const float* pe   = (const float*)d_in[3];
    const float* wq   = (const float*)d_in[4];
    const float* bq   = (const float*)d_in[5];
    const float* wk   = (const float*)d_in[6];
    const float* bk   = (const float*)d_in[7];
    const float* wv   = (const float*)d_in[8];
    const float* bv   = (const float*)d_in[9];
    const float* wo   = (const float*)d_in[10];
    const float* bo   = (const float*)d_in[11];
    const float* w1   = (const float*)d_in[12];
    const float* b1   = (const float*)d_in[13];
    const float* w2   = (const float*)d_in[14];
    const float* b2   = (const float*)d_in[15];
    const float* g1   = (const float*)d_in[16];
    const float* be1  = (const float*)d_in[17];
    const float* g2   = (const float*)d_in[18];
    const float* be2  = (const float*)d_in[19];
    const float* wout = (const float*)d_in[20];
    const float* bout = (const float*)d_in[21];
    float* out = (float*)d_out;

    static float *p_h=nullptr,*p_q,*p_k,*p_v,*p_t,*p_ff;
    if (!p_h) {
        void* p;
        cudaGetSymbolAddress(&p, g_h);  p_h  = (float*)p;
        cudaGetSymbolAddress(&p, g_q);  p_q  = (float*)p;
        cudaGetSymbolAddress(&p, g_k);  p_k  = (float*)p;
        cudaGetSymbolAddress(&p, g_v);  p_v  = (float*)p;
        cudaGetSymbolAddress(&p, g_t);  p_t  = (float*)p;
        cudaGetSymbolAddress(&p, g_ff); p_ff = (float*)p;
    }

    const dim3 gemm_block(16,16);

    // embedding
    embed_kernel<<<(MM*DD + 255)/256, 256>>>(x, emb, pe);

    for (int l = 0; l < LL; l++) {
        const float* wq_l = wq + (size_t)l*DD*DD;
        const float* wk_l = wk + (size_t)l*DD*DD;
        const float* wv_l = wv + (size_t)l*DD*DD;
        const float* wo_l = wo + (size_t)l*DD*DD;
        const float* w1_l = w1 + (size_t)l*DD*DFF;
        const float* w2_l = w2 + (size_t)l*DFF*DD;

        // QKV projections
        dim3 gqkv(DD/64, MM/64);
        sgemm_kernel<<<gqkv, gemm_block>>>(p_h, wq_l, bq + l*DD, p_q, DD, DD, 0);
        sgemm_kernel<<<gqkv, gemm_block>>>(p_h, wk_l, bk + l*DD, p_k, DD, DD, 0);
        sgemm_kernel<<<gqkv, gemm_block>>>(p_h, wv_l, bv + l*DD, p_v, DD, DD, 0);

        // attention: scores+softmax -> attn map region of d_out, then o = a@v
        float* amap_l = out + LOGITS_ELEMS + (size_t)l*AMAP_ELEMS;
        dim3 ga(SS, BB*HH);
        attn_scores_kernel<<<ga, 256>>>(p_q, p_k, amap_l);
        attn_o_kernel<<<ga, 64>>>(amap_l, p_v, p_t);

        // output projection (p_t -> p_q reused as proj result)
        sgemm_kernel<<<gqkv, gemm_block>>>(p_t, wo_l, bo + l*DD, p_q, DD, DD, 0);

        // h = LN(h + o)
        add_ln_kernel<<<MM, 256>>>(p_h, p_q, g1 + l*DD, be1 + l*DD, p_h);

        // FFN
        dim3 gff1(DFF/64, MM/64);
        sgemm_kernel<<<gff1, gemm_block>>>(p_h, w1_l, b1 + l*DFF, p_ff, DD, DFF, 1);
        dim3 gff2(DD/64, MM/64);
        sgemm_kernel<<<gff2, gemm_block>>>(p_ff, w2_l, b2 + l*DD, p_t, DFF, DD, 0);

        // h = LN(h + ff)
        add_ln_kernel<<<MM, 256>>>(p_h, p_t, g2 + l*DD, be2 + l*DD, p_h);
    }

    // logits = h @ wout + bout  -> first region of d_out
    dim3 glog(VV/64, MM/64);
    sgemm_kernel<<<glog, gemm_block>>>(p_h, wout, bout, out, DD, VV, 0);
}

// round 2
// speedup vs baseline: 1.5344x; 1.5344x over previous
#include <cuda_runtime.h>
#include <math.h>
#include <stdint.h>

// Problem dims
#define BB   4
#define SS   1024
#define DD   768
#define HH   12
#define VV   32000
#define LL   2
#define DK   64
#define DFF  3072
#define MM   (BB*SS)          // 4096 rows

#define LOGITS_ELEMS ((size_t)BB*SS*VV)
#define AMAP_ELEMS   ((size_t)BB*HH*SS*SS)

// ---------------- scratch (no allocations allowed) ----------------
__device__ float g_h [MM*DD];
__device__ float g_q [MM*DD];
__device__ float g_k [MM*DD];
__device__ float g_v [MM*DD];
__device__ float g_t [MM*DD];
__device__ float g_ff[MM*DFF];

__device__ __forceinline__ uint32_t f2tf32(float x) {
    uint32_t r;
    asm("cvt.rna.tf32.f32 %0, %1;" : "=r"(r) : "f"(x));
    return r;
}

// ---------------- embedding: h = emb[x]*sqrt(D) + pe[:S] ----------------
__global__ void embed_kernel(const int* __restrict__ x,
                             const float* __restrict__ emb,
                             const float* __restrict__ pe)
{
    int i = blockIdx.x * 256 + threadIdx.x;
    if (i >= MM*DD) return;
    int row = i / DD;
    int d   = i - row*DD;
    int s   = row & (SS-1);
    int tok = x[row];
    g_h[i] = emb[(size_t)tok*DD + d] * 27.712812921102035f + pe[(size_t)s*DD + d];
}

// ---------------- TF32 tensor-core GEMM ------------------------------------
// C[M,N] = A[M,K] @ W[K,N] + bias, optional relu.
// BM=128, BN=128, BK=16. 256 threads = 8 warps (4 x 2), warp tile 32x64.
// mma.sync.aligned.m16n8k8.row.col.f32.tf32.tf32.f32
// Requires: M%128==0, N%128==0, K%16==0.
#define ASTRIDE 132
__global__ __launch_bounds__(256, 2)
void gemm_tf32_kernel(const float* __restrict__ A,
                      const float* __restrict__ W,
                      const float* __restrict__ bias,
                      float* __restrict__ C,
                      int K, int N, int relu)
{
    __shared__ uint32_t As[16][ASTRIDE];   // [k][m], tf32 bits
    __shared__ uint32_t Bs[16][ASTRIDE];   // [k][n], tf32 bits

    const int tid    = threadIdx.x;
    const int wid    = tid >> 5;
    const int lane   = tid & 31;
    const int gr     = lane >> 2;      // group id (0..7)
    const int ctg    = lane & 3;       // thread in group (0..3)
    const int warp_m = wid & 3;        // 0..3  -> 32-row slice
    const int warp_n = wid >> 2;       // 0..1  -> 64-col slice

    const int row0 = blockIdx.y * 128;
    const int col0 = blockIdx.x * 128;

    // A load mapping: m = tid>>1 (0..127), kq = (tid&1)*8
    const int a_m  = tid >> 1;
    const int a_kq = (tid & 1) * 8;
    // B load mapping: kb = tid>>4 (0..15), nq = (tid&15)*8
    const int b_kb = tid >> 4;
    const int b_nq = (tid & 15) * 8;

    float acc[2][8][4];
    #pragma unroll
    for (int i = 0; i < 2; i++)
        #pragma unroll
        for (int j = 0; j < 8; j++)
            #pragma unroll
            for (int q = 0; q < 4; q++) acc[i][j][q] = 0.0f;

    for (int k0 = 0; k0 < K; k0 += 16) {
        // ---- load A tile (128x16) ----
        {
            const float* src = A + (size_t)(row0 + a_m)*K + k0 + a_kq;
            float4 v0 = *(const float4*)(src);
            float4 v1 = *(const float4*)(src + 4);
            As[a_kq+0][a_m] = f2tf32(v0.x);
            As[a_kq+1][a_m] = f2tf32(v0.y);
            As[a_kq+2][a_m] = f2tf32(v0.z);
            As[a_kq+3][a_m] = f2tf32(v0.w);
            As[a_kq+4][a_m] = f2tf32(v1.x);
            As[a_kq+5][a_m] = f2tf32(v1.y);
            As[a_kq+6][a_m] = f2tf32(v1.z);
            As[a_kq+7][a_m] = f2tf32(v1.w);
        }
        // ---- load B tile (16x128) ----
        {
            const float* src = W + (size_t)(k0 + b_kb)*N + col0 + b_nq;
            float4 v0 = *(const float4*)(src);
            float4 v1 = *(const float4*)(src + 4);
            uint32_t* dst = &Bs[b_kb][b_nq];
            dst[0] = f2tf32(v0.x); dst[1] = f2tf32(v0.y);
            dst[2] = f2tf32(v0.z); dst[3] = f2tf32(v0.w);
            dst[4] = f2tf32(v1.x); dst[5] = f2tf32(v1.y);
            dst[6] = f2tf32(v1.z); dst[7] = f2tf32(v1.w);
        }
        __syncthreads();

        #pragma unroll
        for (int kk = 0; kk < 16; kk += 8) {
            // A fragments for 2 m-tiles
            uint32_t af[2][4];
            #pragma unroll
            for (int mt = 0; mt < 2; mt++) {
                int mb = warp_m*32 + mt*16;
                af[mt][0] = As[kk + ctg    ][mb + gr    ];
                af[mt][1] = As[kk + ctg    ][mb + gr + 8];
                af[mt][2] = As[kk + ctg + 4][mb + gr    ];
                af[mt][3] = As[kk + ctg + 4][mb + gr + 8];
            }
            // B fragments for 8 n-tiles
            uint32_t bf[8][2];
            #pragma unroll
            for (int nt = 0; nt < 8; nt++) {
                int nb = warp_n*64 + nt*8;
                bf[nt][0] = Bs[kk + ctg    ][nb + gr];
                bf[nt][1] = Bs[kk + ctg + 4][nb + gr];
            }
            #pragma unroll
            for (int mt = 0; mt < 2; mt++)
                #pragma unroll
                for (int nt = 0; nt < 8; nt++) {
                    asm volatile(
                        "mma.sync.aligned.m16n8k8.row.col.f32.tf32.tf32.f32 "
                        "{%0,%1,%2,%3}, {%4,%5,%6,%7}, {%8,%9}, {%0,%1,%2,%3};"
                        : "+f"(acc[mt][nt][0]), "+f"(acc[mt][nt][1]),
                          "+f"(acc[mt][nt][2]), "+f"(acc[mt][nt][3])
                        : "r"(af[mt][0]), "r"(af[mt][1]),
                          "r"(af[mt][2]), "r"(af[mt][3]),
                          "r"(bf[nt][0]), "r"(bf[nt][1]));
                }
        }
        __syncthreads();
    }

    // ---- epilogue: bias (+relu), write float2 pairs ----
    #pragma unroll
    for (int mt = 0; mt < 2; mt++) {
        int r_base = row0 + warp_m*32 + mt*16 + gr;
        #pragma unroll
        for (int nt = 0; nt < 8; nt++) {
            int c_base = col0 + warp_n*64 + nt*8 + 2*ctg;
            float b0 = bias[c_base], b1 = bias[c_base+1];
            float v0 = acc[mt][nt][0] + b0;
            float v1 = acc[mt][nt][1] + b1;
            float v2 = acc[mt][nt][2] + b0;
            float v3 = acc[mt][nt][3] + b1;
            if (relu) {
                v0 = fmaxf(v0, 0.f); v1 = fmaxf(v1, 0.f);
                v2 = fmaxf(v2, 0.f); v3 = fmaxf(v3, 0.f);
            }
            *(float2*)(C + (size_t)r_base*N + c_base)     = make_float2(v0, v1);
            *(float2*)(C + (size_t)(r_base+8)*N + c_base) = make_float2(v2, v3);
        }
    }
}

// ---------------- attention scores + softmax, writes attn map --------------
__global__ void attn_scores_kernel(const float* __restrict__ Q,
                                   const float* __restrict__ Km,
                                   float* __restrict__ amap)
{
    const int qpos = blockIdx.x;
    const int bh   = blockIdx.y;
    const int b    = bh / HH;
    const int hh   = bh - b*HH;
    const int tid  = threadIdx.x;

    __shared__ float qs[DK];
    __shared__ float sc[SS];
    __shared__ float red[256];

    if (tid < DK)
        qs[tid] = Q[((size_t)(b*SS + qpos))*DD + hh*DK + tid] * 0.125f;
    __syncthreads();

    for (int k = tid; k < SS; k += 256) {
        float dot = -1e30f;
        if (k <= qpos) {
            const float4* kr = (const float4*)(Km + ((size_t)(b*SS + k))*DD + hh*DK);
            const float4* qv = (const float4*)qs;
            dot = 0.0f;
            #pragma unroll
            for (int i = 0; i < 16; i++) {
                float4 kv = kr[i], q4 = qv[i];
                dot += q4.x*kv.x + q4.y*kv.y + q4.z*kv.z + q4.w*kv.w;
            }
        }
        sc[k] = dot;
    }
    __syncthreads();

    float m = -1e30f;
    for (int k = tid; k < SS; k += 256) m = fmaxf(m, sc[k]);
    red[tid] = m; __syncthreads();
    for (int s = 128; s > 0; s >>= 1) {
        if (tid < s) red[tid] = fmaxf(red[tid], red[tid+s]);
        __syncthreads();
    }
    m = red[0];
    __syncthreads();

    float sum = 0.0f;
    for (int k = tid; k < SS; k += 256) {
        float e = (k <= qpos) ? __expf(sc[k] - m) : 0.0f;
        sc[k] = e;
        sum += e;
    }
    red[tid] = sum; __syncthreads();
    for (int s = 128; s > 0; s >>= 1) {
        if (tid < s) red[tid] += red[tid+s];
        __syncthreads();
    }
    float inv = 1.0f / red[0];

    float* arow = amap + ((size_t)bh*SS + qpos)*SS;
    for (int k = tid; k < SS; k += 256) arow[k] = sc[k] * inv;
}

// ---------------- o = a @ v ----------------
__global__ void attn_o_kernel(const float* __restrict__ amap,
                              const float* __restrict__ Vm,
                              float* __restrict__ O)
{
    const int qpos = blockIdx.x;
    const int bh   = blockIdx.y;
    const int b    = bh / HH;
    const int hh   = bh - b*HH;
    const int d    = threadIdx.x;

    const float* arow = amap + ((size_t)bh*SS + qpos)*SS;
    const float* vb   = Vm + ((size_t)(b*SS))*DD + hh*DK + d;

    float acc = 0.0f;
    int kend = qpos + 1;
    #pragma unroll 4
    for (int k = 0; k < kend; k++)
        acc += arow[k] * vb[(size_t)k*DD];

    O[((size_t)(b*SS + qpos))*DD + hh*DK + d] = acc;
}

// ---------------- residual add + layernorm --------------------------------
__global__ void add_ln_kernel(const float* __restrict__ res,
                              const float* __restrict__ x,
                              const float* __restrict__ g,
                              const float* __restrict__ be,
                              float* __restrict__ out)
{
    const int row = blockIdx.x;
    const int tid = threadIdx.x;
    __shared__ float buf[DD];
    __shared__ float red[256];

    float s = 0.0f;
    for (int d = tid; d < DD; d += 256) {
        float v = res[(size_t)row*DD + d] + x[(size_t)row*DD + d];
        buf[d] = v;
        s += v;
    }
    red[tid] = s; __syncthreads();
    for (int t = 128; t > 0; t >>= 1) {
        if (tid < t) red[tid] += red[tid+t];
        __syncthreads();
    }
    float mean = red[0] * (1.0f/DD);
    __syncthreads();

    float vs = 0.0f;
    for (int d = tid; d < DD; d += 256) {
        float dv = buf[d] - mean;
        vs += dv*dv;
    }
    red[tid] = vs; __syncthreads();
    for (int t = 128; t > 0; t >>= 1) {
        if (tid < t) red[tid] += red[tid+t];
        __syncthreads();
    }
    float rstd = rsqrtf(red[0] * (1.0f/DD) + 1e-5f);

    for (int d = tid; d < DD; d += 256)
        out[(size_t)row*DD + d] = (buf[d] - mean)*rstd*g[d] + be[d];
}

// ---------------------------------------------------------------------------
extern "C" void kernel_launch(void* const* d_in, const int* in_sizes, int n_in,
                              void* d_out, int out_size)
{
    (void)in_sizes; (void)n_in; (void)out_size;

    const int*   x    = (const int*)  d_in[0];
    const float* emb  = (const float*)d_in[2];
    const float* pe   = (const float*)d_in[3];
    const float* wq   = (const float*)d_in[4];
    const float* bq   = (const float*)d_in[5];
    const float* wk   = (const float*)d_in[6];
    const float* bk   = (const float*)d_in[7];
    const float* wv   = (const float*)d_in[8];
    const float* bv   = (const float*)d_in[9];
    const float* wo   = (const float*)d_in[10];
    const float* bo   = (const float*)d_in[11];
    const float* w1   = (const float*)d_in[12];
    const float* b1   = (const float*)d_in[13];
    const float* w2   = (const float*)d_in[14];
    const float* b2   = (const float*)d_in[15];
    const float* g1   = (const float*)d_in[16];
    const float* be1  = (const float*)d_in[17];
    const float* g2   = (const float*)d_in[18];
    const float* be2  = (const float*)d_in[19];
    const float* wout = (const float*)d_in[20];
    const float* bout = (const float*)d_in[21];
    float* out = (float*)d_out;

    static float *p_h=nullptr,*p_q,*p_k,*p_v,*p_t,*p_ff;
    if (!p_h) {
        void* p;
        cudaGetSymbolAddress(&p, g_h);  p_h  = (float*)p;
        cudaGetSymbolAddress(&p, g_q);  p_q  = (float*)p;
        cudaGetSymbolAddress(&p, g_k);  p_k  = (float*)p;
        cudaGetSymbolAddress(&p, g_v);  p_v  = (float*)p;
        cudaGetSymbolAddress(&p, g_t);  p_t  = (float*)p;
        cudaGetSymbolAddress(&p, g_ff); p_ff = (float*)p;
    }

    // embedding
    embed_kernel<<<(MM*DD + 255)/256, 256>>>(x, emb, pe);

    for (int l = 0; l < LL; l++) {
        const float* wq_l = wq + (size_t)l*DD*DD;
        const float* wk_l = wk + (size_t)l*DD*DD;
        const float* wv_l = wv + (size_t)l*DD*DD;
        const float* wo_l = wo + (size_t)l*DD*DD;
        const float* w1_l = w1 + (size_t)l*DD*DFF;
        const float* w2_l = w2 + (size_t)l*DFF*DD;

        // QKV projections (tensor core)
        dim3 gqkv(DD/128, MM/128);
        gemm_tf32_kernel<<<gqkv, 256>>>(p_h, wq_l, bq + l*DD, p_q, DD, DD, 0);
        gemm_tf32_kernel<<<gqkv, 256>>>(p_h, wk_l, bk + l*DD, p_k, DD, DD, 0);
        gemm_tf32_kernel<<<gqkv, 256>>>(p_h, wv_l, bv + l*DD, p_v, DD, DD, 0);

        // attention
        float* amap_l = out + LOGITS_ELEMS + (size_t)l*AMAP_ELEMS;
        dim3 ga(SS, BB*HH);
        attn_scores_kernel<<<ga, 256>>>(p_q, p_k, amap_l);
        attn_o_kernel<<<ga, 64>>>(amap_l, p_v, p_t);

        // output projection
        gemm_tf32_kernel<<<gqkv, 256>>>(p_t, wo_l, bo + l*DD, p_q, DD, DD, 0);

        // h = LN(h + o)
        add_ln_kernel<<<MM, 256>>>(p_h, p_q, g1 + l*DD, be1 + l*DD, p_h);

        // FFN
        dim3 gff1(DFF/128, MM/128);
        gemm_tf32_kernel<<<gff1, 256>>>(p_h, w1_l, b1 + l*DFF, p_ff, DD, DFF, 1);
        dim3 gff2(DD/128, MM/128);
        gemm_tf32_kernel<<<gff2, 256>>>(p_ff, w2_l, b2 + l*DD, p_t, DFF, DD, 0);

        // h = LN(h + ff)
        add_ln_kernel<<<MM, 256>>>(p_h, p_t, g2 + l*DD, be2 + l*DD, p_h);
    }

    // logits
    dim3 glog(VV/128, MM/128);
    gemm_tf32_kernel<<<glog, 256>>>(p_h, wout, bout, out, DD, VV, 0);
}

// round 3
// speedup vs baseline: 1.9398x; 1.2642x over previous
#include <cuda_runtime.h>
#include <math.h>
#include <stdint.h>

#define BB   4
#define SS   1024
#define DD   768
#define HH   12
#define VV   32000
#define LL   2
#define DK   64
#define DFF  3072
#define MM   (BB*SS)

#define LOGITS_ELEMS ((size_t)BB*SS*VV)
#define AMAP_ELEMS   ((size_t)BB*HH*SS*SS)

// ---------------- scratch ----------------
__device__ float g_h [MM*DD];
__device__ float g_q [MM*DD];
__device__ float g_k [MM*DD];
__device__ float g_v [MM*DD];
__device__ float g_t [MM*DD];
__device__ float g_ff[MM*DFF];

__device__ __forceinline__ uint32_t f2tf32(float x) {
    uint32_t r;
    asm("cvt.rna.tf32.f32 %0, %1;" : "=r"(r) : "f"(x));
    return r;
}
__device__ __forceinline__ void cp_async16(void* sdst, const void* gsrc) {
    uint32_t s = (uint32_t)__cvta_generic_to_shared(sdst);
    asm volatile("cp.async.cg.shared.global [%0], [%1], 16;" :: "r"(s), "l"(gsrc));
}
#define CP_COMMIT() asm volatile("cp.async.commit_group;")
#define CP_WAIT(n)  asm volatile("cp.async.wait_group %0;" :: "n"(n))

// ---------------- embedding ----------------
__global__ void embed_kernel(const int* __restrict__ x,
                             const float* __restrict__ emb,
                             const float* __restrict__ pe)
{
    int i = blockIdx.x * 256 + threadIdx.x;
    if (i >= MM*DD) return;
    int row = i / DD;
    int d   = i - row*DD;
    int s   = row & (SS-1);
    int tok = x[row];
    g_h[i] = emb[(size_t)tok*DD + d] * 27.712812921102035f + pe[(size_t)s*DD + d];
}

// ---------------- pipelined TF32 tensor-core GEMM -------------------------
// C[M,N] = A[M,K] @ W[K,N] + bias, opt relu.
// BM=128, BN=128, BK=32, double-buffered cp.async. 256 thr = 8 warps (4x2),
// warp tile 32x64. grid: (M/128, N/128).
#define AS_PAD 36
#define BS_PAD 132
#define GEMM_SMEM ((2*128*AS_PAD + 2*32*BS_PAD)*4)

__global__ __launch_bounds__(256)
void gemm_tf32_kernel(const float* __restrict__ A,
                      const float* __restrict__ W,
                      const float* __restrict__ bias,
                      float* __restrict__ C,
                      int K, int N, int relu)
{
    extern __shared__ float smem[];
    float* As = smem;                    // [2][128][AS_PAD]  (m-major)
    float* Bs = smem + 2*128*AS_PAD;     // [2][32][BS_PAD]   (k-major)
#define ASM(b,m,k) As[((b)*128+(m))*AS_PAD+(k)]
#define BSM(b,k,n) Bs[((b)*32+(k))*BS_PAD+(n)]

    const int tid    = threadIdx.x;
    const int wid    = tid >> 5;
    const int lane   = tid & 31;
    const int gr     = lane >> 2;
    const int ctg    = lane & 3;
    const int warp_m = wid & 3;
    const int warp_n = wid >> 2;

    const int row0 = blockIdx.x * 128;
    const int col0 = blockIdx.y * 128;

    const int a_m  = tid >> 1;
    const int a_kq = (tid & 1) * 16;
    const int b_k  = tid >> 3;
    const int b_nq = (tid & 7) * 16;

    const float* a_src = A + (size_t)(row0 + a_m)*K + a_kq;
    const float* b_src = W + (size_t)b_k*N + col0 + b_nq;

    float acc[2][8][4] = {};

    const int nt = K >> 5;

    // prologue: tile 0 -> buf 0
    #pragma unroll
    for (int i = 0; i < 4; i++) cp_async16(&ASM(0, a_m, a_kq + 4*i), a_src + 4*i);
    #pragma unroll
    for (int i = 0; i < 4; i++) cp_async16(&BSM(0, b_k, b_nq + 4*i), b_src + 4*i);
    CP_COMMIT();

    for (int t = 0; t < nt; t++) {
        const int cur = t & 1;
        if (t + 1 < nt) {
            const int nb = cur ^ 1;
            const int k0 = (t+1) << 5;
            #pragma unroll
            for (int i = 0; i < 4; i++)
                cp_async16(&ASM(nb, a_m, a_kq + 4*i), a_src + k0 + 4*i);
            #pragma unroll
            for (int i = 0; i < 4; i++)
                cp_async16(&BSM(nb, b_k, b_nq + 4*i), b_src + (size_t)k0*N + 4*i);
            CP_COMMIT();
            CP_WAIT(1);
        } else {
            CP_WAIT(0);
        }
        __syncthreads();

        #pragma unroll
        for (int kk = 0; kk < 32; kk += 8) {
            uint32_t af[2][4];
            #pragma unroll
            for (int mt = 0; mt < 2; mt++) {
                int mb = warp_m*32 + mt*16;
                af[mt][0] = f2tf32(ASM(cur, mb+gr,   kk+ctg));
                af[mt][1] = f2tf32(ASM(cur, mb+gr+8, kk+ctg));
                af[mt][2] = f2tf32(ASM(cur, mb+gr,   kk+ctg+4));
                af[mt][3] = f2tf32(ASM(cur, mb+gr+8, kk+ctg+4));
            }
            uint32_t bf[8][2];
            #pragma unroll
            for (int ntl = 0; ntl < 8; ntl++) {
                int nb = warp_n*64 + ntl*8;
                bf[ntl][0] = f2tf32(BSM(cur, kk+ctg,   nb+gr));
                bf[ntl][1] = f2tf32(BSM(cur, kk+ctg+4, nb+gr));
            }
            #pragma unroll
            for (int mt = 0; mt < 2; mt++)
                #pragma unroll
                for (int ntl = 0; ntl < 8; ntl++)
                    asm volatile(
                        "mma.sync.aligned.m16n8k8.row.col.f32.tf32.tf32.f32 "
                        "{%0,%1,%2,%3}, {%4,%5,%6,%7}, {%8,%9}, {%0,%1,%2,%3};"
                        : "+f"(acc[mt][ntl][0]), "+f"(acc[mt][ntl][1]),
                          "+f"(acc[mt][ntl][2]), "+f"(acc[mt][ntl][3])
                        : "r"(af[mt][0]), "r"(af[mt][1]),
                          "r"(af[mt][2]), "r"(af[mt][3]),
                          "r"(bf[ntl][0]), "r"(bf[ntl][1]));
        }
        __syncthreads();
    }

    #pragma unroll
    for (int mt = 0; mt < 2; mt++) {
        int r_base = row0 + warp_m*32 + mt*16 + gr;
        #pragma unroll
        for (int ntl = 0; ntl < 8; ntl++) {
            int c_base = col0 + warp_n*64 + ntl*8 + 2*ctg;
            float b0 = bias[c_base], b1 = bias[c_base+1];
            float v0 = acc[mt][ntl][0] + b0;
            float v1 = acc[mt][ntl][1] + b1;
            float v2 = acc[mt][ntl][2] + b0;
            float v3 = acc[mt][ntl][3] + b1;
            if (relu) {
                v0 = fmaxf(v0, 0.f); v1 = fmaxf(v1, 0.f);
                v2 = fmaxf(v2, 0.f); v3 = fmaxf(v3, 0.f);
            }
            *(float2*)(C + (size_t)r_base*N + c_base)     = make_float2(v0, v1);
            *(float2*)(C + (size_t)(r_base+8)*N + c_base) = make_float2(v2, v3);
        }
    }
#undef ASM
#undef BSM
}

// ---------------- attention scores + softmax -------------------------------
__global__ void attn_scores_kernel(const float* __restrict__ Q,
                                   const float* __restrict__ Km,
                                   float* __restrict__ amap)
{
    const int qpos = blockIdx.x;
    const int bh   = blockIdx.y;
    const int b    = bh / HH;
    const int hh   = bh - b*HH;
    const int tid  = threadIdx.x;

    __shared__ float qs[DK];
    __shared__ float sc[SS];
    __shared__ float red[256];

    if (tid < DK)
        qs[tid] = Q[((size_t)(b*SS + qpos))*DD + hh*DK + tid] * 0.125f;
    __syncthreads();

    for (int k = tid; k < SS; k += 256) {
        float dot = -1e30f;
        if (k <= qpos) {
            const float4* kr = (const float4*)(Km + ((size_t)(b*SS + k))*DD + hh*DK);
            const float4* qv = (const float4*)qs;
            dot = 0.0f;
            #pragma unroll
            for (int i = 0; i < 16; i++) {
                float4 kv = kr[i], q4 = qv[i];
                dot += q4.x*kv.x + q4.y*kv.y + q4.z*kv.z + q4.w*kv.w;
            }
        }
        sc[k] = dot;
    }
    __syncthreads();

    float m = -1e30f;
    for (int k = tid; k < SS; k += 256) m = fmaxf(m, sc[k]);
    red[tid] = m; __syncthreads();
    for (int s = 128; s > 0; s >>= 1) {
        if (tid < s) red[tid] = fmaxf(red[tid], red[tid+s]);
        __syncthreads();
    }
    m = red[0];
    __syncthreads();

    float sum = 0.0f;
    for (int k = tid; k < SS; k += 256) {
        float e = (k <= qpos) ? __expf(sc[k] - m) : 0.0f;
        sc[k] = e;
        sum += e;
    }
    red[tid] = sum; __syncthreads();
    for (int s = 128; s > 0; s >>= 1) {
        if (tid < s) red[tid] += red[tid+s];
        __syncthreads();
    }
    float inv = 1.0f / red[0];

    float* arow = amap + ((size_t)bh*SS + qpos)*SS;
    for (int k = tid; k < SS; k += 256) arow[k] = sc[k] * inv;
}

// ---------------- attn_o: O = amap @ V  (tensor core, causal block skip) ---
// BM=128 (q), BN=64 (dk), BK=32 (kpos). grid (SS/128, BB*HH).
// amap has exact zeros above the diagonal, so no masking needed.
#define BO_PAD 68
#define ATTN_SMEM ((2*128*AS_PAD + 2*32*BO_PAD)*4)
__global__ __launch_bounds__(256)
void attn_o_mma_kernel(const float* __restrict__ amap,
                       const float* __restrict__ Vm,
                       float* __restrict__ O)
{
    extern __shared__ float smem[];
    float* As = smem;                    // [2][128][AS_PAD]
    float* Bs = smem + 2*128*AS_PAD;     // [2][32][BO_PAD]
#define ASM(b,m,k) As[((b)*128+(m))*AS_PAD+(k)]
#define BSM(b,k,n) Bs[((b)*32+(k))*BO_PAD+(n)]

    const int tid    = threadIdx.x;
    const int wid    = tid >> 5;
    const int lane   = tid & 31;
    const int gr     = lane >> 2;
    const int ctg    = lane & 3;
    const int warp_m = wid & 3;     // 32-row slice
    const int warp_n = wid >> 2;    // 32-col slice

    const int row0 = blockIdx.x * 128;
    const int bh   = blockIdx.y;
    const int b    = bh / HH;
    const int hh   = bh - b*HH;

    const float* Arow = amap + (size_t)bh*SS*SS;          // [SS][SS]
    const float* Vb   = Vm + (size_t)(b*SS)*DD + hh*DK;   // rows stride DD

    const int a_m  = tid >> 1;
    const int a_kq = (tid & 1) * 16;
    const int b_k  = tid >> 3;
    const int b_nq = (tid & 7) * 8;

    const float* a_src = Arow + (size_t)(row0 + a_m)*SS + a_kq;
    const float* b_src = Vb + (size_t)b_k*DD + b_nq;

    float acc[2][4][4] = {};

    const int nt = (row0 + 128) >> 5;   // causal: only k < row0+128

    #pragma unroll
    for (int i = 0; i < 4; i++) cp_async16(&ASM(0, a_m, a_kq + 4*i), a_src + 4*i);
    #pragma unroll
    for (int i = 0; i < 2; i++) cp_async16(&BSM(0, b_k, b_nq + 4*i), b_src + 4*i);
    CP_COMMIT();

    for (int t = 0; t < nt; t++) {
        const int cur = t & 1;
        if (t + 1 < nt) {
            const int nb = cur ^ 1;
            const int k0 = (t+1) << 5;
            #pragma unroll
            for (int i = 0; i < 4; i++)
                cp_async16(&ASM(nb, a_m, a_kq + 4*i), a_src + k0 + 4*i);
            #pragma unroll
            for (int i = 0; i < 2; i++)
                cp_async16(&BSM(nb, b_k, b_nq + 4*i), b_src + (size_t)k0*DD + 4*i);
            CP_COMMIT();
            CP_WAIT(1);
        } else {
            CP_WAIT(0);
        }
        __syncthreads();

        #pragma unroll
        for (int kk = 0; kk < 32; kk += 8) {
            uint32_t af[2][4];
            #pragma unroll
            for (int mt = 0; mt < 2; mt++) {
                int mb = warp_m*32 + mt*16;
                af[mt][0] = f2tf32(ASM(cur, mb+gr,   kk+ctg));
                af[mt][1] = f2tf32(ASM(cur, mb+gr+8, kk+ctg));
                af[mt][2] = f2tf32(ASM(cur, mb+gr,   kk+ctg+4));
                af[mt][3] = f2tf32(ASM(cur, mb+gr+8, kk+ctg+4));
            }
            uint32_t bf[4][2];
            #pragma unroll
            for (int ntl = 0; ntl < 4; ntl++) {
                int nb = warp_n*32 + ntl*8;
                bf[ntl][0] = f2tf32(BSM(cur, kk+ctg,   nb+gr));
                bf[ntl][1] = f2tf32(BSM(cur, kk+ctg+4, nb+gr));
            }
            #pragma unroll
            for (int mt = 0; mt < 2; mt++)
                #pragma unroll
                for (int ntl = 0; ntl < 4; ntl++)
                    asm volatile(
                        "mma.sync.aligned.m16n8k8.row.col.f32.tf32.tf32.f32 "
                        "{%0,%1,%2,%3}, {%4,%5,%6,%7}, {%8,%9}, {%0,%1,%2,%3};"
                        : "+f"(acc[mt][ntl][0]), "+f"(acc[mt][ntl][1]),
                          "+f"(acc[mt][ntl][2]), "+f"(acc[mt][ntl][3])
                        : "r"(af[mt][0]), "r"(af[mt][1]),
                          "r"(af[mt][2]), "r"(af[mt][3]),
                          "r"(bf[ntl][0]), "r"(bf[ntl][1]));
        }
        __syncthreads();
    }

    #pragma unroll
    for (int mt = 0; mt < 2; mt++) {
        int r = row0 + warp_m*32 + mt*16 + gr;
        #pragma unroll
        for (int ntl = 0; ntl < 4; ntl++) {
            int c = warp_n*32 + ntl*8 + 2*ctg;
            float* dst = O + (size_t)(b*SS + r)*DD + hh*DK + c;
            *(float2*)dst = make_float2(acc[mt][ntl][0], acc[mt][ntl][1]);
            *(float2*)(dst + 8*DD) = make_float2(acc[mt][ntl][2], acc[mt][ntl][3]);
        }
    }
#undef ASM
#undef BSM
}

// ---------------- residual add + layernorm --------------------------------
__global__ void add_ln_kernel(const float* __restrict__ res,
                              const float* __restrict__ x,
                              const float* __restrict__ g,
                              const float* __restrict__ be,
                              float* __restrict__ out)
{
    const int row = blockIdx.x;
    const int tid = threadIdx.x;
    __shared__ float buf[DD];
    __shared__ float red[256];

    float s = 0.0f;
    for (int d = tid; d < DD; d += 256) {
        float v = res[(size_t)row*DD + d] + x[(size_t)row*DD + d];
        buf[d] = v;
        s += v;
    }
    red[tid] = s; __syncthreads();
    for (int t = 128; t > 0; t >>= 1) {
        if (tid < t) red[tid] += red[tid+t];
        __syncthreads();
    }
    float mean = red[0] * (1.0f/DD);
    __syncthreads();

    float vs = 0.0f;
    for (int d = tid; d < DD; d += 256) {
        float dv = buf[d] - mean;
        vs += dv*dv;
    }
    red[tid] = vs; __syncthreads();
    for (int t = 128; t > 0; t >>= 1) {
        if (tid < t) red[tid] += red[tid+t];
        __syncthreads();
    }
    float rstd = rsqrtf(red[0] * (1.0f/DD) + 1e-5f);

    for (int d = tid; d < DD; d += 256)
        out[(size_t)row*DD + d] = (buf[d] - mean)*rstd*g[d] + be[d];
}

// ---------------------------------------------------------------------------
extern "C" void kernel_launch(void* const* d_in, const int* in_sizes, int n_in,
                              void* d_out, int out_size)
{
    (void)in_sizes; (void)n_in; (void)out_size;

    const int*   x    = (const int*)  d_in[0];
    const float* emb  = (const float*)d_in[2];
    const float* pe   = (const float*)d_in[3];
    const float* wq   = (const float*)d_in[4];
    const float* bq   = (const float*)d_in[5];
    const float* wk   = (const float*)d_in[6];
    const float* bk   = (const float*)d_in[7];
    const float* wv   = (const float*)d_in[8];
    const float* bv   = (const float*)d_in[9];
    const float* wo   = (const float*)d_in[10];
    const float* bo   = (const float*)d_in[11];
    const float* w1   = (const float*)d_in[12];
    const float* b1   = (const float*)d_in[13];
    const float* w2   = (const float*)d_in[14];
    const float* b2   = (const float*)d_in[15];
    const float* g1   = (const float*)d_in[16];
    const float* be1  = (const float*)d_in[17];
    const float* g2   = (const float*)d_in[18];
    const float* be2  = (const float*)d_in[19];
    const float* wout = (const float*)d_in[20];
    const float* bout = (const float*)d_in[21];
    float* out = (float*)d_out;

    static float *p_h=nullptr,*p_q,*p_k,*p_v,*p_t,*p_ff;
    if (!p_h) {
        void* p;
        cudaGetSymbolAddress(&p, g_h);  p_h  = (float*)p;
        cudaGetSymbolAddress(&p, g_q);  p_q  = (float*)p;
        cudaGetSymbolAddress(&p, g_k);  p_k  = (float*)p;
        cudaGetSymbolAddress(&p, g_v);  p_v  = (float*)p;
        cudaGetSymbolAddress(&p, g_t);  p_t  = (float*)p;
        cudaGetSymbolAddress(&p, g_ff); p_ff = (float*)p;
        cudaFuncSetAttribute(gemm_tf32_kernel,
            cudaFuncAttributeMaxDynamicSharedMemorySize, GEMM_SMEM);
        cudaFuncSetAttribute(attn_o_mma_kernel,
            cudaFuncAttributeMaxDynamicSharedMemorySize, ATTN_SMEM);
    }

    embed_kernel<<<(MM*DD + 255)/256, 256>>>(x, emb, pe);

    for (int l = 0; l < LL; l++) {
        const float* wq_l = wq + (size_t)l*DD*DD;
        const float* wk_l = wk + (size_t)l*DD*DD;
        const float* wv_l = wv + (size_t)l*DD*DD;
        const float* wo_l = wo + (size_t)l*DD*DD;
        const float* w1_l = w1 + (size_t)l*DD*DFF;
        const float* w2_l = w2 + (size_t)l*DFF*DD;

        dim3 gqkv(MM/128, DD/128);
        gemm_tf32_kernel<<<gqkv, 256, GEMM_SMEM>>>(p_h, wq_l, bq + l*DD, p_q, DD, DD, 0);
        gemm_tf32_kernel<<<gqkv, 256, GEMM_SMEM>>>(p_h, wk_l, bk + l*DD, p_k, DD, DD, 0);
        gemm_tf32_kernel<<<gqkv, 256, GEMM_SMEM>>>(p_h, wv_l, bv + l*DD, p_v, DD, DD, 0);

        float* amap_l = out + LOGITS_ELEMS + (size_t)l*AMAP_ELEMS;
        dim3 ga(SS, BB*HH);
        attn_scores_kernel<<<ga, 256>>>(p_q, p_k, amap_l);

        dim3 gao(SS/128, BB*HH);
        attn_o_mma_kernel<<<gao, 256, ATTN_SMEM>>>(amap_l, p_v, p_t);

        gemm_tf32_kernel<<<gqkv, 256, GEMM_SMEM>>>(p_t, wo_l, bo + l*DD, p_q, DD, DD, 0);
        add_ln_kernel<<<MM, 256>>>(p_h, p_q, g1 + l*DD, be1 + l*DD, p_h);

        dim3 gff1(MM/128, DFF/128);
        gemm_tf32_kernel<<<gff1, 256, GEMM_SMEM>>>(p_h, w1_l, b1 + l*DFF, p_ff, DD, DFF, 1);
        dim3 gff2(MM/128, DD/128);
        gemm_tf32_kernel<<<gff2, 256, GEMM_SMEM>>>(p_ff, w2_l, b2 + l*DD, p_t, DFF, DD, 0);

        add_ln_kernel<<<MM, 256>>>(p_h, p_t, g2 + l*DD, be2 + l*DD, p_h);
    }

    dim3 glog(MM/128, VV/128);
    gemm_tf32_kernel<<<glog, 256, GEMM_SMEM>>>(p_h, wout, bout, out, DD, VV, 0);
}

// round 4
// speedup vs baseline: 3.4296x; 1.7680x over previous
#include <cuda_runtime.h>
#include <math.h>
#include <stdint.h>

#define BB   4
#define SS   1024
#define DD   768
#define HH   12
#define VV   32000
#define LL   2
#define DK   64
#define DFF  3072
#define MM   (BB*SS)

#define LOGITS_ELEMS ((size_t)BB*SS*VV)
#define AMAP_ELEMS   ((size_t)BB*HH*SS*SS)

// ---------------- scratch ----------------
__device__ float g_h [MM*DD];
__device__ float g_q [MM*DD];
__device__ float g_k [MM*DD];
__device__ float g_v [MM*DD];
__device__ float g_t [MM*DD];
__device__ float g_ff[MM*DFF];

__device__ __forceinline__ uint32_t f2tf32(float x) {
    uint32_t r;
    asm("cvt.rna.tf32.f32 %0, %1;" : "=r"(r) : "f"(x));
    return r;
}
__device__ __forceinline__ void cp_async16(void* sdst, const void* gsrc) {
    uint32_t s = (uint32_t)__cvta_generic_to_shared(sdst);
    asm volatile("cp.async.cg.shared.global [%0], [%1], 16;" :: "r"(s), "l"(gsrc));
}
#define CP_COMMIT() asm volatile("cp.async.commit_group;")
#define CP_WAIT(n)  asm volatile("cp.async.wait_group %0;" :: "n"(n))

#define LDSM4(R0,R1,R2,R3,ADDR) \
    asm volatile("ldmatrix.sync.aligned.m8n8.x4.shared.b16 {%0,%1,%2,%3}, [%4];" \
        : "=r"(R0), "=r"(R1), "=r"(R2), "=r"(R3) : "r"(ADDR))

#define MMA_TF32(ACC, AF, B0, B1) \
    asm volatile("mma.sync.aligned.m16n8k8.row.col.f32.tf32.tf32.f32 " \
        "{%0,%1,%2,%3}, {%4,%5,%6,%7}, {%8,%9}, {%0,%1,%2,%3};" \
        : "+f"((ACC)[0]), "+f"((ACC)[1]), "+f"((ACC)[2]), "+f"((ACC)[3]) \
        : "r"((AF)[0]), "r"((AF)[1]), "r"((AF)[2]), "r"((AF)[3]), \
          "r"(B0), "r"(B1))

// ---------------- embedding ----------------
__global__ void embed_kernel(const int* __restrict__ x,
                             const float* __restrict__ emb,
                             const float* __restrict__ pe)
{
    int i = blockIdx.x * 256 + threadIdx.x;
    if (i >= MM*DD) return;
    int row = i / DD;
    int d   = i - row*DD;
    int s   = row & (SS-1);
    int tok = x[row];
    g_h[i] = emb[(size_t)tok*DD + d] * 27.712812921102035f + pe[(size_t)s*DD + d];
}

// ============ dense TF32 GEMM: 3-stage cp.async, ldmatrix A ===============
// C[M,N] = A[M,K] @ W[K,N] + bias, opt relu. BM=128 BN=128 BK=32.
// 8 warps: warp_m=wid>>2 (64 rows), warp_n=wid&3 (32 cols). mt=4, nt=4.
#define A_STR 36    // floats per A smem row (32 + 4 pad) -> 144B
#define B_STR 136   // floats per B smem row (128 + 8 pad)
#define A_TILE_F (128*A_STR)
#define B_TILE_F (32*B_STR)
#define GEMM_SMEM (3*(A_TILE_F + B_TILE_F)*4)

__global__ __launch_bounds__(256, 2)
void gemm_tf32_kernel(const float* __restrict__ A,
                      const float* __restrict__ W,
                      const float* __restrict__ bias,
                      float* __restrict__ C,
                      int K, int N, int relu)
{
    extern __shared__ float smem[];
    float* As = smem;
    float* Bs = smem + 3*A_TILE_F;

    const int tid    = threadIdx.x;
    const int wid    = tid >> 5;
    const int lane   = tid & 31;
    const int gr     = lane >> 2;
    const int ctg    = lane & 3;
    const int warp_m = wid >> 2;   // 0..1
    const int warp_n = wid & 3;    // 0..3

    const int row0 = blockIdx.x * 128;
    const int col0 = blockIdx.y * 128;

    // loader mappings
    const int a_m  = tid >> 1;
    const int a_kq = (tid & 1) * 16;
    const int b_k  = tid >> 3;
    const int b_nq = (tid & 7) * 16;

    // ldmatrix lane geometry
    const int row_a = ((lane >> 3) & 1) * 8 + (lane & 7);
    const int col_a = (lane >> 4) * 4;

    const uint32_t as_base = (uint32_t)__cvta_generic_to_shared(As);

    float acc[4][4][4] = {};

    const int ntiles = K >> 5;

#define G_ISSUE(tile, slot) do { \
    const float* ag = A + (size_t)(row0 + a_m)*K + (tile)*32 + a_kq; \
    float* ad = &As[(slot)*A_TILE_F + a_m*A_STR + a_kq]; \
    cp_async16(ad,    ag);    cp_async16(ad+4,  ag+4); \
    cp_async16(ad+8,  ag+8);  cp_async16(ad+12, ag+12); \
    const float* bg = W + ((size_t)(tile)*32 + b_k)*N + col0 + b_nq; \
    float* bd = &Bs[(slot)*B_TILE_F + b_k*B_STR + b_nq]; \
    cp_async16(bd,    bg);    cp_async16(bd+4,  bg+4); \
    cp_async16(bd+8,  bg+8);  cp_async16(bd+12, bg+12); \
} while (0)

    // prologue: tiles 0,1 -> slots 0,1 (one commit group each)
    G_ISSUE(0, 0); CP_COMMIT();
    G_ISSUE(1, 1); CP_COMMIT();

    for (int t = 0; t < ntiles; t++) {
        const int s = t % 3;
        CP_WAIT(1);
        __syncthreads();
        {
            const int tn = t + 2;
            if (tn < ntiles) G_ISSUE(tn, tn % 3);
            CP_COMMIT();   // always one group per iter (empty ok)
        }

        #pragma unroll
        for (int kk = 0; kk < 32; kk += 8) {
            uint32_t af[4][4];
            #pragma unroll
            for (int mt = 0; mt < 4; mt++) {
                uint32_t addr = as_base + 4u*((uint32_t)(s*A_TILE_F)
                              + (uint32_t)((warp_m*64 + mt*16 + row_a)*A_STR)
                              + (uint32_t)(col_a + kk));
                LDSM4(af[mt][0], af[mt][1], af[mt][2], af[mt][3], addr);
                #pragma unroll
                for (int i = 0; i < 4; i++)
                    af[mt][i] = f2tf32(__uint_as_float(af[mt][i]));
            }
            uint32_t bf[4][2];
            #pragma unroll
            for (int nt = 0; nt < 4; nt++) {
                const float* bp = &Bs[s*B_TILE_F + (kk+ctg)*B_STR + warp_n*32 + nt*8 + gr];
                bf[nt][0] = f2tf32(bp[0]);
                bf[nt][1] = f2tf32(bp[4*B_STR]);
            }
            #pragma unroll
            for (int mt = 0; mt < 4; mt++)
                #pragma unroll
                for (int nt = 0; nt < 4; nt++)
                    MMA_TF32(acc[mt][nt], af[mt], bf[nt][0], bf[nt][1]);
        }
    }
#undef G_ISSUE

    #pragma unroll
    for (int mt = 0; mt < 4; mt++) {
        int r_base = row0 + warp_m*64 + mt*16 + gr;
        #pragma unroll
        for (int nt = 0; nt < 4; nt++) {
            int c_base = col0 + warp_n*32 + nt*8 + 2*ctg;
            float b0 = bias[c_base], b1 = bias[c_base+1];
            float v0 = acc[mt][nt][0] + b0;
            float v1 = acc[mt][nt][1] + b1;
            float v2 = acc[mt][nt][2] + b0;
            float v3 = acc[mt][nt][3] + b1;
            if (relu) {
                v0 = fmaxf(v0, 0.f); v1 = fmaxf(v1, 0.f);
                v2 = fmaxf(v2, 0.f); v3 = fmaxf(v3, 0.f);
            }
            *(float2*)(C + (size_t)r_base*N + c_base)     = make_float2(v0, v1);
            *(float2*)(C + (size_t)(r_base+8)*N + c_base) = make_float2(v2, v3);
        }
    }
}

// ============ attention scores pass A: S = Q @ K^T (block-causal) =========
// Per (b,h): M=N=1024, K=64. Only lower+diagonal 128x128 blocks (36 per bh).
// Both operands row-major [seq][DK] with row stride DD -> n-major smem,
// fragments via ldmatrix for A and B. Single-stage (K tiny). Raw scores
// (scaled by 0.125) written to amap; softmax pass normalizes.
#define S_STR 68    // 64 + 4 pad -> 272B rows
#define SCORES_SMEM (2*128*S_STR*4)

__global__ __launch_bounds__(256)
void attn_scores_gemm(const float* __restrict__ Q,
                      const float* __restrict__ Kmat,
                      float* __restrict__ amap)
{
    extern __shared__ float smem[];
    float* As = smem;              // Q tile  [128][S_STR]
    float* Bs = smem + 128*S_STR;  // K tile  [128][S_STR]

    const int tid    = threadIdx.x;
    const int wid    = tid >> 5;
    const int lane   = tid & 31;
    const int gr     = lane >> 2;
    const int ctg    = lane & 3;
    const int warp_m = wid >> 2;
    const int warp_n = wid & 3;

    // triangular block index -> (qb, kb)
    int idx = blockIdx.x;
    int qb = 0;
    while ((qb+1)*(qb+2)/2 <= idx) qb++;
    int kb = idx - qb*(qb+1)/2;

    const int bh = blockIdx.y;
    const int b  = bh / HH;
    const int hh = bh - b*HH;

    const int row0 = qb * 128;
    const int col0 = kb * 128;

    const float* Qb = Q    + (size_t)(b*SS)*DD + hh*DK;
    const float* Kb = Kmat + (size_t)(b*SS)*DD + hh*DK;

    const int l_m  = tid >> 1;
    const int l_kq = (tid & 1) * 32;

    // fill both tiles (8 cp16 each)
    {
        const float* ag = Qb + (size_t)(row0 + l_m)*DD + l_kq;
        float* ad = &As[l_m*S_STR + l_kq];
        #pragma unroll
        for (int i = 0; i < 8; i++) cp_async16(ad + 4*i, ag + 4*i);
        const float* bg = Kb + (size_t)(col0 + l_m)*DD + l_kq;
        float* bd = &Bs[l_m*S_STR + l_kq];
        #pragma unroll
        for (int i = 0; i < 8; i++) cp_async16(bd + 4*i, bg + 4*i);
    }
    CP_COMMIT();
    CP_WAIT(0);
    __syncthreads();

    const int row_a = ((lane >> 3) & 1) * 8 + (lane & 7);
    const int col_a = (lane >> 4) * 4;
    const uint32_t as_base = (uint32_t)__cvta_generic_to_shared(As);
    const uint32_t bs_base = (uint32_t)__cvta_generic_to_shared(Bs);

    float acc[4][4][4] = {};

    #pragma unroll
    for (int kk = 0; kk < 64; kk += 8) {
        uint32_t af[4][4];
        #pragma unroll
        for (int mt = 0; mt < 4; mt++) {
            uint32_t addr = as_base + 4u*(uint32_t)((warp_m*64 + mt*16 + row_a)*S_STR + col_a + kk);
            LDSM4(af[mt][0], af[mt][1], af[mt][2], af[mt][3], addr);
            #pragma unroll
            for (int i = 0; i < 4; i++)
                af[mt][i] = f2tf32(__uint_as_float(af[mt][i]));
        }
        uint32_t bf[4][2];
        #pragma unroll
        for (int p = 0; p < 2; p++) {
            uint32_t addr = bs_base + 4u*(uint32_t)((warp_n*32 + p*16 + row_a)*S_STR + col_a + kk);
            uint32_t r0, r1, r2, r3;
            LDSM4(r0, r1, r2, r3, addr);
            bf[2*p  ][0] = f2tf32(__uint_as_float(r0));
            bf[2*p+1][0] = f2tf32(__uint_as_float(r1));
            bf[2*p  ][1] = f2tf32(__uint_as_float(r2));
            bf[2*p+1][1] = f2tf32(__uint_as_float(r3));
        }
        #pragma unroll
        for (int mt = 0; mt < 4; mt++)
            #pragma unroll
            for (int nt = 0; nt < 4; nt++)
                MMA_TF32(acc[mt][nt], af[mt], bf[nt][0], bf[nt][1]);
    }

    float* Sb = amap + (size_t)bh*SS*SS;
    #pragma unroll
    for (int mt = 0; mt < 4; mt++) {
        int r = row0 + warp_m*64 + mt*16 + gr;
        #pragma unroll
        for (int nt = 0; nt < 4; nt++) {
            int c = col0 + warp_n*32 + nt*8 + 2*ctg;
            *(float2*)(Sb + (size_t)r*SS + c) =
                make_float2(acc[mt][nt][0]*0.125f, acc[mt][nt][1]*0.125f);
            *(float2*)(Sb + (size_t)(r+8)*SS + c) =
                make_float2(acc[mt][nt][2]*0.125f, acc[mt][nt][3]*0.125f);
        }
    }
}

// ============ softmax pass B: rowwise, in place, zero above diagonal ======
__global__ void softmax_rows(float* __restrict__ amap)
{
    const int qpos = blockIdx.x;
    const int bh   = blockIdx.y;
    const int tid  = threadIdx.x;
    const int wid  = tid >> 5;
    const int lane = tid & 31;

    float* row = amap + ((size_t)bh*SS + qpos)*SS;

    __shared__ float sc[SS];
    __shared__ float red[8];
    __shared__ float bcast;

    float m = -1e30f;
    for (int k = tid; k <= qpos; k += 256) {
        float v = row[k];
        sc[k] = v;
        m = fmaxf(m, v);
    }
    #pragma unroll
    for (int o = 16; o > 0; o >>= 1) m = fmaxf(m, __shfl_xor_sync(0xffffffffu, m, o));
    if (lane == 0) red[wid] = m;
    __syncthreads();
    if (tid == 0) {
        float mm = red[0];
        #pragma unroll
        for (int i = 1; i < 8; i++) mm = fmaxf(mm, red[i]);
        bcast = mm;
    }
    __syncthreads();
    m = bcast;

    float s = 0.0f;
    for (int k = tid; k <= qpos; k += 256) {
        float e = __expf(sc[k] - m);
        sc[k] = e;
        s += e;
    }
    #pragma unroll
    for (int o = 16; o > 0; o >>= 1) s += __shfl_xor_sync(0xffffffffu, s, o);
    if (lane == 0) red[wid] = s;
    __syncthreads();
    if (tid == 0) {
        float ss = red[0];
        #pragma unroll
        for (int i = 1; i < 8; i++) ss += red[i];
        bcast = 1.0f / ss;
    }
    __syncthreads();
    float inv = bcast;

    for (int k = tid; k < SS; k += 256)
        row[k] = (k <= qpos) ? sc[k] * inv : 0.0f;
}

// ============ attn_o: O = amap @ V (known-good from R3) ===================
#define AS_PAD 36
#define BO_PAD 68
#define ATTN_SMEM ((2*128*AS_PAD + 2*32*BO_PAD)*4)
__global__ __launch_bounds__(256)
void attn_o_mma_kernel(const float* __restrict__ amap,
                       const float* __restrict__ Vm,
                       float* __restrict__ O)
{
    extern __shared__ float smem[];
    float* As = smem;
    float* Bs = smem + 2*128*AS_PAD;
#define ASM(b,m,k) As[((b)*128+(m))*AS_PAD+(k)]
#define BSM(b,k,n) Bs[((b)*32+(k))*BO_PAD+(n)]

    const int tid    = threadIdx.x;
    const int wid    = tid >> 5;
    const int lane   = tid & 31;
    const int gr     = lane >> 2;
    const int ctg    = lane & 3;
    const int warp_m = wid & 3;
    const int warp_n = wid >> 2;

    const int row0 = blockIdx.x * 128;
    const int bh   = blockIdx.y;
    const int b    = bh / HH;
    const int hh   = bh - b*HH;

    const float* Arow = amap + (size_t)bh*SS*SS;
    const float* Vb   = Vm + (size_t)(b*SS)*DD + hh*DK;

    const int a_m  = tid >> 1;
    const int a_kq = (tid & 1) * 16;
    const int b_k  = tid >> 3;
    const int b_nq = (tid & 7) * 8;

    const float* a_src = Arow + (size_t)(row0 + a_m)*SS + a_kq;
    const float* b_src = Vb + (size_t)b_k*DD + b_nq;

    float acc[2][4][4] = {};

    const int nt = (row0 + 128) >> 5;

    #pragma unroll
    for (int i = 0; i < 4; i++) cp_async16(&ASM(0, a_m, a_kq + 4*i), a_src + 4*i);
    #pragma unroll
    for (int i = 0; i < 2; i++) cp_async16(&BSM(0, b_k, b_nq + 4*i), b_src + 4*i);
    CP_COMMIT();

    for (int t = 0; t < nt; t++) {
        const int cur = t & 1;
        if (t + 1 < nt) {
            const int nb = cur ^ 1;
            const int k0 = (t+1) << 5;
            #pragma unroll
            for (int i = 0; i < 4; i++)
                cp_async16(&ASM(nb, a_m, a_kq + 4*i), a_src + k0 + 4*i);
            #pragma unroll
            for (int i = 0; i < 2; i++)
                cp_async16(&BSM(nb, b_k, b_nq + 4*i), b_src + (size_t)k0*DD + 4*i);
            CP_COMMIT();
            CP_WAIT(1);
        } else {
            CP_WAIT(0);
        }
        __syncthreads();

        #pragma unroll
        for (int kk = 0; kk < 32; kk += 8) {
            uint32_t af[2][4];
            #pragma unroll
            for (int mt = 0; mt < 2; mt++) {
                int mb = warp_m*32 + mt*16;
                af[mt][0] = f2tf32(ASM(cur, mb+gr,   kk+ctg));
                af[mt][1] = f2tf32(ASM(cur, mb+gr+8, kk+ctg));
                af[mt][2] = f2tf32(ASM(cur, mb+gr,   kk+ctg+4));
                af[mt][3] = f2tf32(ASM(cur, mb+gr+8, kk+ctg+4));
            }
            uint32_t bf[4][2];
            #pragma unroll
            for (int ntl = 0; ntl < 4; ntl++) {
                int nb = warp_n*32 + ntl*8;
                bf[ntl][0] = f2tf32(BSM(cur, kk+ctg,   nb+gr));
                bf[ntl][1] = f2tf32(BSM(cur, kk+ctg+4, nb+gr));
            }
            #pragma unroll
            for (int mt = 0; mt < 2; mt++)
                #pragma unroll
                for (int ntl = 0; ntl < 4; ntl++)
                    MMA_TF32(acc[mt][ntl], af[mt], bf[ntl][0], bf[ntl][1]);
        }
        __syncthreads();
    }

    #pragma unroll
    for (int mt = 0; mt < 2; mt++) {
        int r = row0 + warp_m*32 + mt*16 + gr;
        #pragma unroll
        for (int ntl = 0; ntl < 4; ntl++) {
            int c = warp_n*32 + ntl*8 + 2*ctg;
            float* dst = O + (size_t)(b*SS + r)*DD + hh*DK + c;
            *(float2*)dst = make_float2(acc[mt][ntl][0], acc[mt][ntl][1]);
            *(float2*)(dst + 8*DD) = make_float2(acc[mt][ntl][2], acc[mt][ntl][3]);
        }
    }
#undef ASM
#undef BSM
}

// ---------------- residual add + layernorm --------------------------------
__global__ void add_ln_kernel(const float* __restrict__ res,
                              const float* __restrict__ x,
                              const float* __restrict__ g,
                              const float* __restrict__ be,
                              float* __restrict__ out)
{
    const int row = blockIdx.x;
    const int tid = threadIdx.x;
    __shared__ float buf[DD];
    __shared__ float red[256];

    float s = 0.0f;
    for (int d = tid; d < DD; d += 256) {
        float v = res[(size_t)row*DD + d] + x[(size_t)row*DD + d];
        buf[d] = v;
        s += v;
    }
    red[tid] = s; __syncthreads();
    for (int t = 128; t > 0; t >>= 1) {
        if (tid < t) red[tid] += red[tid+t];
        __syncthreads();
    }
    float mean = red[0] * (1.0f/DD);
    __syncthreads();

    float vs = 0.0f;
    for (int d = tid; d < DD; d += 256) {
        float dv = buf[d] - mean;
        vs += dv*dv;
    }
    red[tid] = vs; __syncthreads();
    for (int t = 128; t > 0; t >>= 1) {
        if (tid < t) red[tid] += red[tid+t];
        __syncthreads();
    }
    float rstd = rsqrtf(red[0] * (1.0f/DD) + 1e-5f);

    for (int d = tid; d < DD; d += 256)
        out[(size_t)row*DD + d] = (buf[d] - mean)*rstd*g[d] + be[d];
}

// ---------------------------------------------------------------------------
extern "C" void kernel_launch(void* const* d_in, const int* in_sizes, int n_in,
                              void* d_out, int out_size)
{
    (void)in_sizes; (void)n_in; (void)out_size;

    const int*   x    = (const int*)  d_in[0];
    const float* emb  = (const float*)d_in[2];
    const float* pe   = (const float*)d_in[3];
    const float* wq   = (const float*)d_in[4];
    const float* bq   = (const float*)d_in[5];
    const float* wk   = (const float*)d_in[6];
    const float* bk   = (const float*)d_in[7];
    const float* wv   = (const float*)d_in[8];
    const float* bv   = (const float*)d_in[9];
    const float* wo   = (const float*)d_in[10];
    const float* bo   = (const float*)d_in[11];
    const float* w1   = (const float*)d_in[12];
    const float* b1   = (const float*)d_in[13];
    const float* w2   = (const float*)d_in[14];
    const float* b2   = (const float*)d_in[15];
    const float* g1   = (const float*)d_in[16];
    const float* be1  = (const float*)d_in[17];
    const float* g2   = (const float*)d_in[18];
    const float* be2  = (const float*)d_in[19];
    const float* wout = (const float*)d_in[20];
    const float* bout = (const float*)d_in[21];
    float* out = (float*)d_out;

    static float *p_h=nullptr,*p_q,*p_k,*p_v,*p_t,*p_ff;
    if (!p_h) {
        void* p;
        cudaGetSymbolAddress(&p, g_h);  p_h  = (float*)p;
        cudaGetSymbolAddress(&p, g_q);  p_q  = (float*)p;
        cudaGetSymbolAddress(&p, g_k);  p_k  = (float*)p;
        cudaGetSymbolAddress(&p, g_v);  p_v  = (float*)p;
        cudaGetSymbolAddress(&p, g_t);  p_t  = (float*)p;
        cudaGetSymbolAddress(&p, g_ff); p_ff = (float*)p;
        cudaFuncSetAttribute(gemm_tf32_kernel,
            cudaFuncAttributeMaxDynamicSharedMemorySize, GEMM_SMEM);
        cudaFuncSetAttribute(attn_scores_gemm,
            cudaFuncAttributeMaxDynamicSharedMemorySize, SCORES_SMEM);
        cudaFuncSetAttribute(attn_o_mma_kernel,
            cudaFuncAttributeMaxDynamicSharedMemorySize, ATTN_SMEM);
    }

    embed_kernel<<<(MM*DD + 255)/256, 256>>>(x, emb, pe);

    for (int l = 0; l < LL; l++) {
        const float* wq_l = wq + (size_t)l*DD*DD;
        const float* wk_l = wk + (size_t)l*DD*DD;
        const float* wv_l = wv + (size_t)l*DD*DD;
        const float* wo_l = wo + (size_t)l*DD*DD;
        const float* w1_l = w1 + (size_t)l*DD*DFF;
        const float* w2_l = w2 + (size_t)l*DFF*DD;

        dim3 gqkv(MM/128, DD/128);
        gemm_tf32_kernel<<<gqkv, 256, GEMM_SMEM>>>(p_h, wq_l, bq + l*DD, p_q, DD, DD, 0);
        gemm_tf32_kernel<<<gqkv, 256, GEMM_SMEM>>>(p_h, wk_l, bk + l*DD, p_k, DD, DD, 0);
        gemm_tf32_kernel<<<gqkv, 256, GEMM_SMEM>>>(p_h, wv_l, bv + l*DD, p_v, DD, DD, 0);

        float* amap_l = out + LOGITS_ELEMS + (size_t)l*AMAP_ELEMS;

        dim3 gsc(36, BB*HH);
        attn_scores_gemm<<<gsc, 256, SCORES_SMEM>>>(p_q, p_k, amap_l);

        dim3 gsm(SS, BB*HH);
        softmax_rows<<<gsm, 256>>>(amap_l);

        dim3 gao(SS/128, BB*HH);
        attn_o_mma_kernel<<<gao, 256, ATTN_SMEM>>>(amap_l, p_v, p_t);

        gemm_tf32_kernel<<<gqkv, 256, GEMM_SMEM>>>(p_t, wo_l, bo + l*DD, p_q, DD, DD, 0);
        add_ln_kernel<<<MM, 256>>>(p_h, p_q, g1 + l*DD, be1 + l*DD, p_h);

        dim3 gff1(MM/128, DFF/128);
        gemm_tf32_kernel<<<gff1, 256, GEMM_SMEM>>>(p_h, w1_l, b1 + l*DFF, p_ff, DD, DFF, 1);
        dim3 gff2(MM/128, DD/128);
        gemm_tf32_kernel<<<gff2, 256, GEMM_SMEM>>>(p_ff, w2_l, b2 + l*DD, p_t, DFF, DD, 0);

        add_ln_kernel<<<MM, 256>>>(p_h, p_t, g2 + l*DD, be2 + l*DD, p_h);
    }

    dim3 glog(MM/128, VV/128);
    gemm_tf32_kernel<<<glog, 256, GEMM_SMEM>>>(p_h, wout, bout, out, DD, VV, 0);
}

// round 5
// speedup vs baseline: 3.7996x; 1.1079x over previous
#include <cuda_runtime.h>
#include <math.h>
#include <stdint.h>

#define BB   4
#define SS   1024
#define DD   768
#define HH   12
#define VV   32000
#define LL   2
#define DK   64
#define DFF  3072
#define MM   (BB*SS)
#define QSTR (3*DD)          // fused qkv row stride

#define LOGITS_ELEMS ((size_t)BB*SS*VV)
#define AMAP_ELEMS   ((size_t)BB*HH*SS*SS)

// ---------------- scratch ----------------
__device__ float g_h  [MM*DD];
__device__ float g_qkv[MM*QSTR];
__device__ float g_t  [MM*DD];
__device__ float g_p  [MM*DD];
__device__ float g_ff [MM*DFF];
__device__ float g_at [MM*DFF];      // tf32 copy of current A operand
__device__ float g_wt [DD*VV];       // tf32 copy of current W operand
__device__ float g_b3 [QSTR];        // concat qkv bias

__device__ __forceinline__ uint32_t f2tf32(float x) {
    uint32_t r;
    asm("cvt.rna.tf32.f32 %0, %1;" : "=r"(r) : "f"(x));
    return r;
}
__device__ __forceinline__ float tf32r(float x) {
    return __uint_as_float(f2tf32(x));
}
__device__ __forceinline__ void cp_async16(void* sdst, const void* gsrc) {
    uint32_t s = (uint32_t)__cvta_generic_to_shared(sdst);
    asm volatile("cp.async.cg.shared.global [%0], [%1], 16;" :: "r"(s), "l"(gsrc));
}
#define CP_COMMIT() asm volatile("cp.async.commit_group;")
#define CP_WAIT(n)  asm volatile("cp.async.wait_group %0;" :: "n"(n))

#define LDSM4(R0,R1,R2,R3,ADDR) \
    asm volatile("ldmatrix.sync.aligned.m8n8.x4.shared.b16 {%0,%1,%2,%3}, [%4];" \
        : "=r"(R0), "=r"(R1), "=r"(R2), "=r"(R3) : "r"(ADDR))

#define MMA_TF32(ACC, AF, B0, B1) \
    asm volatile("mma.sync.aligned.m16n8k8.row.col.f32.tf32.tf32.f32 " \
        "{%0,%1,%2,%3}, {%4,%5,%6,%7}, {%8,%9}, {%0,%1,%2,%3};" \
        : "+f"((ACC)[0]), "+f"((ACC)[1]), "+f"((ACC)[2]), "+f"((ACC)[3]) \
        : "r"((AF)[0]), "r"((AF)[1]), "r"((AF)[2]), "r"((AF)[3]), \
          "r"(B0), "r"(B1))

// ---------------- tf32 pre-conversion kernels -----------------------------
__global__ void cvt_tf32_kernel(const float4* __restrict__ src,
                                float4* __restrict__ dst, int n4)
{
    int i = blockIdx.x * 256 + threadIdx.x;
    if (i >= n4) return;
    float4 v = src[i];
    v.x = tf32r(v.x); v.y = tf32r(v.y); v.z = tf32r(v.z); v.w = tf32r(v.w);
    dst[i] = v;
}
// strided column write (for packing qkv weights into [K][2304])
__global__ void cvt_tf32_cols_kernel(const float* __restrict__ src,
                                     float* __restrict__ dst,
                                     int rows, int cols, int dstr, int coff)
{
    int i = blockIdx.x * 256 + threadIdx.x;
    int c4 = cols >> 2;
    if (i >= rows * c4) return;
    int r = i / c4;
    int c = (i - r*c4) << 2;
    float4 v = *(const float4*)(src + (size_t)r*cols + c);
    v.x = tf32r(v.x); v.y = tf32r(v.y); v.z = tf32r(v.z); v.w = tf32r(v.w);
    *(float4*)(dst + (size_t)r*dstr + coff + c) = v;
}
__global__ void concat3_kernel(const float* __restrict__ a,
                               const float* __restrict__ b,
                               const float* __restrict__ c,
                               float* __restrict__ dst)
{
    int i = blockIdx.x * 256 + threadIdx.x;
    if (i >= QSTR) return;
    dst[i] = (i < DD) ? a[i] : (i < 2*DD ? b[i-DD] : c[i-2*DD]);
}

// ---------------- embedding ----------------
__global__ void embed_kernel(const int* __restrict__ x,
                             const float* __restrict__ emb,
                             const float* __restrict__ pe)
{
    int i = blockIdx.x * 256 + threadIdx.x;
    if (i >= MM*DD) return;
    int row = i / DD;
    int d   = i - row*DD;
    int s   = row & (SS-1);
    int tok = x[row];
    g_h[i] = emb[(size_t)tok*DD + d] * 27.712812921102035f + pe[(size_t)s*DD + d];
}

// ============ dense TF32 GEMM (operands pre-converted, NO cvt inside) =====
// C[M,N] = A[M,K] @ W[K,N] + bias, opt relu. BM=128 BN=128 BK=32, 3-stage.
#define A_STR 36
#define B_STR 136
#define A_TILE_F (128*A_STR)
#define B_TILE_F (32*B_STR)
#define GEMM_SMEM (3*(A_TILE_F + B_TILE_F)*4)

__global__ __launch_bounds__(256, 2)
void gemm_tf32_kernel(const float* __restrict__ A,
                      const float* __restrict__ W,
                      const float* __restrict__ bias,
                      float* __restrict__ C,
                      int K, int N, int relu)
{
    extern __shared__ float smem[];
    float* As = smem;
    float* Bs = smem + 3*A_TILE_F;

    const int tid    = threadIdx.x;
    const int wid    = tid >> 5;
    const int lane   = tid & 31;
    const int gr     = lane >> 2;
    const int ctg    = lane & 3;
    const int warp_m = wid >> 2;
    const int warp_n = wid & 3;

    const int row0 = blockIdx.x * 128;
    const int col0 = blockIdx.y * 128;

    const int a_m  = tid >> 1;
    const int a_kq = (tid & 1) * 16;
    const int b_k  = tid >> 3;
    const int b_nq = (tid & 7) * 16;

    const int row_a = ((lane >> 3) & 1) * 8 + (lane & 7);
    const int col_a = (lane >> 4) * 4;

    const uint32_t as_base = (uint32_t)__cvta_generic_to_shared(As);

    float acc[4][4][4] = {};
    const int ntiles = K >> 5;

#define G_ISSUE(tile, slot) do { \
    const float* ag = A + (size_t)(row0 + a_m)*K + (tile)*32 + a_kq; \
    float* ad = &As[(slot)*A_TILE_F + a_m*A_STR + a_kq]; \
    cp_async16(ad,    ag);    cp_async16(ad+4,  ag+4); \
    cp_async16(ad+8,  ag+8);  cp_async16(ad+12, ag+12); \
    const float* bg = W + ((size_t)(tile)*32 + b_k)*N + col0 + b_nq; \
    float* bd = &Bs[(slot)*B_TILE_F + b_k*B_STR + b_nq]; \
    cp_async16(bd,    bg);    cp_async16(bd+4,  bg+4); \
    cp_async16(bd+8,  bg+8);  cp_async16(bd+12, bg+12); \
} while (0)

    G_ISSUE(0, 0); CP_COMMIT();
    G_ISSUE(1, 1); CP_COMMIT();

    for (int t = 0; t < ntiles; t++) {
        const int s = t % 3;
        CP_WAIT(1);
        __syncthreads();
        {
            const int tn = t + 2;
            if (tn < ntiles) G_ISSUE(tn, tn % 3);
            CP_COMMIT();
        }

        #pragma unroll
        for (int kk = 0; kk < 32; kk += 8) {
            uint32_t af[4][4];
            #pragma unroll
            for (int mt = 0; mt < 4; mt++) {
                uint32_t addr = as_base + 4u*((uint32_t)(s*A_TILE_F)
                              + (uint32_t)((warp_m*64 + mt*16 + row_a)*A_STR)
                              + (uint32_t)(col_a + kk));
                LDSM4(af[mt][0], af[mt][1], af[mt][2], af[mt][3], addr);
            }
            uint32_t bf[4][2];
            #pragma unroll
            for (int nt = 0; nt < 4; nt++) {
                const float* bp = &Bs[s*B_TILE_F + (kk+ctg)*B_STR + warp_n*32 + nt*8 + gr];
                bf[nt][0] = __float_as_uint(bp[0]);
                bf[nt][1] = __float_as_uint(bp[4*B_STR]);
            }
            #pragma unroll
            for (int mt = 0; mt < 4; mt++)
                #pragma unroll
                for (int nt = 0; nt < 4; nt++)
                    MMA_TF32(acc[mt][nt], af[mt], bf[nt][0], bf[nt][1]);
        }
    }
#undef G_ISSUE

    #pragma unroll
    for (int mt = 0; mt < 4; mt++) {
        int r_base = row0 + warp_m*64 + mt*16 + gr;
        #pragma unroll
        for (int nt = 0; nt < 4; nt++) {
            int c_base = col0 + warp_n*32 + nt*8 + 2*ctg;
            float b0 = bias[c_base], b1 = bias[c_base+1];
            float v0 = acc[mt][nt][0] + b0;
            float v1 = acc[mt][nt][1] + b1;
            float v2 = acc[mt][nt][2] + b0;
            float v3 = acc[mt][nt][3] + b1;
            if (relu) {
                v0 = fmaxf(v0, 0.f); v1 = fmaxf(v1, 0.f);
                v2 = fmaxf(v2, 0.f); v3 = fmaxf(v3, 0.f);
            }
            *(float2*)(C + (size_t)r_base*N + c_base)     = make_float2(v0, v1);
            *(float2*)(C + (size_t)(r_base+8)*N + c_base) = make_float2(v2, v3);
        }
    }
}

// ============ attention scores: S = Q @ K^T (block-causal, fused qkv) =====
#define S_STR 68
#define SCORES_SMEM (2*128*S_STR*4)

__global__ __launch_bounds__(256)
void attn_scores_gemm(const float* __restrict__ qkv,
                      float* __restrict__ amap)
{
    extern __shared__ float smem[];
    float* As = smem;
    float* Bs = smem + 128*S_STR;

    const int tid    = threadIdx.x;
    const int wid    = tid >> 5;
    const int lane   = tid & 31;
    const int gr     = lane >> 2;
    const int ctg    = lane & 3;
    const int warp_m = wid >> 2;
    const int warp_n = wid & 3;

    int idx = blockIdx.x;
    int qb = 0;
    while ((qb+1)*(qb+2)/2 <= idx) qb++;
    int kb = idx - qb*(qb+1)/2;

    const int bh = blockIdx.y;
    const int b  = bh / HH;
    const int hh = bh - b*HH;

    const int row0 = qb * 128;
    const int col0 = kb * 128;

    const float* Qb = qkv + (size_t)(b*SS)*QSTR + hh*DK;
    const float* Kb = Qb + DD;

    const int l_m  = tid >> 1;
    const int l_kq = (tid & 1) * 32;

    {
        const float* ag = Qb + (size_t)(row0 + l_m)*QSTR + l_kq;
        float* ad = &As[l_m*S_STR + l_kq];
        #pragma unroll
        for (int i = 0; i < 8; i++) cp_async16(ad + 4*i, ag + 4*i);
        const float* bg = Kb + (size_t)(col0 + l_m)*QSTR + l_kq;
        float* bd = &Bs[l_m*S_STR + l_kq];
        #pragma unroll
        for (int i = 0; i < 8; i++) cp_async16(bd + 4*i, bg + 4*i);
    }
    CP_COMMIT();
    CP_WAIT(0);
    __syncthreads();

    const int row_a = ((lane >> 3) & 1) * 8 + (lane & 7);
    const int col_a = (lane >> 4) * 4;
    const uint32_t as_base = (uint32_t)__cvta_generic_to_shared(As);
    const uint32_t bs_base = (uint32_t)__cvta_generic_to_shared(Bs);

    float acc[4][4][4] = {};

    #pragma unroll
    for (int kk = 0; kk < 64; kk += 8) {
        uint32_t af[4][4];
        #pragma unroll
        for (int mt = 0; mt < 4; mt++) {
            uint32_t addr = as_base + 4u*(uint32_t)((warp_m*64 + mt*16 + row_a)*S_STR + col_a + kk);
            LDSM4(af[mt][0], af[mt][1], af[mt][2], af[mt][3], addr);
            #pragma unroll
            for (int i = 0; i < 4; i++)
                af[mt][i] = f2tf32(__uint_as_float(af[mt][i]));
        }
        uint32_t bf[4][2];
        #pragma unroll
        for (int p = 0; p < 2; p++) {
            uint32_t addr = bs_base + 4u*(uint32_t)((warp_n*32 + p*16 + row_a)*S_STR + col_a + kk);
            uint32_t r0, r1, r2, r3;
            LDSM4(r0, r1, r2, r3, addr);
            bf[2*p  ][0] = f2tf32(__uint_as_float(r0));
            bf[2*p+1][0] = f2tf32(__uint_as_float(r1));
            bf[2*p  ][1] = f2tf32(__uint_as_float(r2));
            bf[2*p+1][1] = f2tf32(__uint_as_float(r3));
        }
        #pragma unroll
        for (int mt = 0; mt < 4; mt++)
            #pragma unroll
            for (int nt = 0; nt < 4; nt++)
                MMA_TF32(acc[mt][nt], af[mt], bf[nt][0], bf[nt][1]);
    }

    float* Sb = amap + (size_t)bh*SS*SS;
    #pragma unroll
    for (int mt = 0; mt < 4; mt++) {
        int r = row0 + warp_m*64 + mt*16 + gr;
        #pragma unroll
        for (int nt = 0; nt < 4; nt++) {
            int c = col0 + warp_n*32 + nt*8 + 2*ctg;
            *(float2*)(Sb + (size_t)r*SS + c) =
                make_float2(acc[mt][nt][0]*0.125f, acc[mt][nt][1]*0.125f);
            *(float2*)(Sb + (size_t)(r+8)*SS + c) =
                make_float2(acc[mt][nt][2]*0.125f, acc[mt][nt][3]*0.125f);
        }
    }
}

// ============ softmax rows, in place ======================================
__global__ void softmax_rows(float* __restrict__ amap)
{
    const int qpos = blockIdx.x;
    const int bh   = blockIdx.y;
    const int tid  = threadIdx.x;
    const int wid  = tid >> 5;
    const int lane = tid & 31;

    float* row = amap + ((size_t)bh*SS + qpos)*SS;

    __shared__ float sc[SS];
    __shared__ float red[8];
    __shared__ float bcast;

    float m = -1e30f;
    for (int k = tid; k <= qpos; k += 256) {
        float v = row[k];
        sc[k] = v;
        m = fmaxf(m, v);
    }
    #pragma unroll
    for (int o = 16; o > 0; o >>= 1) m = fmaxf(m, __shfl_xor_sync(0xffffffffu, m, o));
    if (lane == 0) red[wid] = m;
    __syncthreads();
    if (tid == 0) {
        float mm = red[0];
        #pragma unroll
        for (int i = 1; i < 8; i++) mm = fmaxf(mm, red[i]);
        bcast = mm;
    }
    __syncthreads();
    m = bcast;

    float s = 0.0f;
    for (int k = tid; k <= qpos; k += 256) {
        float e = __expf(sc[k] - m);
        sc[k] = e;
        s += e;
    }
    #pragma unroll
    for (int o = 16; o > 0; o >>= 1) s += __shfl_xor_sync(0xffffffffu, s, o);
    if (lane == 0) red[wid] = s;
    __syncthreads();
    if (tid == 0) {
        float ss = red[0];
        #pragma unroll
        for (int i = 1; i < 8; i++) ss += red[i];
        bcast = 1.0f / ss;
    }
    __syncthreads();
    float inv = bcast;

    for (int k = tid; k < SS; k += 256)
        row[k] = (k <= qpos) ? sc[k] * inv : 0.0f;
}

// ============ attn_o: O = amap @ V (V from fused qkv) =====================
#define AS_PAD 36
#define BO_PAD 68
#define ATTN_SMEM ((2*128*AS_PAD + 2*32*BO_PAD)*4)
__global__ __launch_bounds__(256)
void attn_o_mma_kernel(const float* __restrict__ amap,
                       const float* __restrict__ qkv,
                       float* __restrict__ O)
{
    extern __shared__ float smem[];
    float* As = smem;
    float* Bs = smem + 2*128*AS_PAD;
#define ASM(b,m,k) As[((b)*128+(m))*AS_PAD+(k)]
#define BSM(b,k,n) Bs[((b)*32+(k))*BO_PAD+(n)]

    const int tid    = threadIdx.x;
    const int wid    = tid >> 5;
    const int lane   = tid & 31;
    const int gr     = lane >> 2;
    const int ctg    = lane & 3;
    const int warp_m = wid & 3;
    const int warp_n = wid >> 2;

    const int row0 = blockIdx.x * 128;
    const int bh   = blockIdx.y;
    const int b    = bh / HH;
    const int hh   = bh - b*HH;

    const float* Arow = amap + (size_t)bh*SS*SS;
    const float* Vb   = qkv + (size_t)(b*SS)*QSTR + 2*DD + hh*DK;

    const int a_m  = tid >> 1;
    const int a_kq = (tid & 1) * 16;
    const int b_k  = tid >> 3;
    const int b_nq = (tid & 7) * 8;

    const float* a_src = Arow + (size_t)(row0 + a_m)*SS + a_kq;
    const float* b_src = Vb + (size_t)b_k*QSTR + b_nq;

    float acc[2][4][4] = {};
    const int nt = (row0 + 128) >> 5;

    #pragma unroll
    for (int i = 0; i < 4; i++) cp_async16(&ASM(0, a_m, a_kq + 4*i), a_src + 4*i);
    #pragma unroll
    for (int i = 0; i < 2; i++) cp_async16(&BSM(0, b_k, b_nq + 4*i), b_src + 4*i);
    CP_COMMIT();

    for (int t = 0; t < nt; t++) {
        const int cur = t & 1;
        if (t + 1 < nt) {
            const int nb = cur ^ 1;
            const int k0 = (t+1) << 5;
            #pragma unroll
            for (int i = 0; i < 4; i++)
                cp_async16(&ASM(nb, a_m, a_kq + 4*i), a_src + k0 + 4*i);
            #pragma unroll
            for (int i = 0; i < 2; i++)
                cp_async16(&BSM(nb, b_k, b_nq + 4*i), b_src + (size_t)k0*QSTR + 4*i);
            CP_COMMIT();
            CP_WAIT(1);
        } else {
            CP_WAIT(0);
        }
        __syncthreads();

        #pragma unroll
        for (int kk = 0; kk < 32; kk += 8) {
            uint32_t af[2][4];
            #pragma unroll
            for (int mt = 0; mt < 2; mt++) {
                int mb = warp_m*32 + mt*16;
                af[mt][0] = f2tf32(ASM(cur, mb+gr,   kk+ctg));
                af[mt][1] = f2tf32(ASM(cur, mb+gr+8, kk+ctg));
                af[mt][2] = f2tf32(ASM(cur, mb+gr,   kk+ctg+4));
                af[mt][3] = f2tf32(ASM(cur, mb+gr+8, kk+ctg+4));
            }
            uint32_t bf[4][2];
            #pragma unroll
            for (int ntl = 0; ntl < 4; ntl++) {
                int nb = warp_n*32 + ntl*8;
                bf[ntl][0] = f2tf32(BSM(cur, kk+ctg,   nb+gr));
                bf[ntl][1] = f2tf32(BSM(cur, kk+ctg+4, nb+gr));
            }
            #pragma unroll
            for (int mt = 0; mt < 2; mt++)
                #pragma unroll
                for (int ntl = 0; ntl < 4; ntl++)
                    MMA_TF32(acc[mt][ntl], af[mt], bf[ntl][0], bf[ntl][1]);
        }
        __syncthreads();
    }

    #pragma unroll
    for (int mt = 0; mt < 2; mt++) {
        int r = row0 + warp_m*32 + mt*16 + gr;
        #pragma unroll
        for (int ntl = 0; ntl < 4; ntl++) {
            int c = warp_n*32 + ntl*8 + 2*ctg;
            float* dst = O + (size_t)(b*SS + r)*DD + hh*DK + c;
            *(float2*)dst = make_float2(acc[mt][ntl][0], acc[mt][ntl][1]);
            *(float2*)(dst + 8*DD) = make_float2(acc[mt][ntl][2], acc[mt][ntl][3]);
        }
    }
#undef ASM
#undef BSM
}

// ---------------- residual add + layernorm --------------------------------
__global__ void add_ln_kernel(const float* __restrict__ res,
                              const float* __restrict__ x,
                              const float* __restrict__ g,
                              const float* __restrict__ be,
                              float* __restrict__ out)
{
    const int row = blockIdx.x;
    const int tid = threadIdx.x;
    __shared__ float buf[DD];
    __shared__ float red[256];

    float s = 0.0f;
    for (int d = tid; d < DD; d += 256) {
        float v = res[(size_t)row*DD + d] + x[(size_t)row*DD + d];
        buf[d] = v;
        s += v;
    }
    red[tid] = s; __syncthreads();
    for (int t = 128; t > 0; t >>= 1) {
        if (tid < t) red[tid] += red[tid+t];
        __syncthreads();
    }
    float mean = red[0] * (1.0f/DD);
    __syncthreads();

    float vs = 0.0f;
    for (int d = tid; d < DD; d += 256) {
        float dv = buf[d] - mean;
        vs += dv*dv;
    }
    red[tid] = vs; __syncthreads();
    for (int t = 128; t > 0; t >>= 1) {
        if (tid < t) red[tid] += red[tid+t];
        __syncthreads();
    }
    float rstd = rsqrtf(red[0] * (1.0f/DD) + 1e-5f);

    for (int d = tid; d < DD; d += 256)
        out[(size_t)row*DD + d] = (buf[d] - mean)*rstd*g[d] + be[d];
}

// ---------------------------------------------------------------------------
static inline void cvt(const float* src, float* dst, size_t n) {
    int n4 = (int)(n >> 2);
    cvt_tf32_kernel<<<(n4 + 255)/256, 256>>>((const float4*)src, (float4*)dst, n4);
}

extern "C" void kernel_launch(void* const* d_in, const int* in_sizes, int n_in,
                              void* d_out, int out_size)
{
    (void)in_sizes; (void)n_in; (void)out_size;

    const int*   x    = (const int*)  d_in[0];
    const float* emb  = (const float*)d_in[2];
    const float* pe   = (const float*)d_in[3];
    const float* wq   = (const float*)d_in[4];
    const float* bq   = (const float*)d_in[5];
    const float* wk   = (const float*)d_in[6];
    const float* bk   = (const float*)d_in[7];
    const float* wv   = (const float*)d_in[8];
    const float* bv   = (const float*)d_in[9];
    const float* wo   = (const float*)d_in[10];
    const float* bo   = (const float*)d_in[11];
    const float* w1   = (const float*)d_in[12];
    const float* b1   = (const float*)d_in[13];
    const float* w2   = (const float*)d_in[14];
    const float* b2   = (const float*)d_in[15];
    const float* g1   = (const float*)d_in[16];
    const float* be1  = (const float*)d_in[17];
    const float* g2   = (const float*)d_in[18];
    const float* be2  = (const float*)d_in[19];
    const float* wout = (const float*)d_in[20];
    const float* bout = (const float*)d_in[21];
    float* out = (float*)d_out;

    static float *p_h=nullptr,*p_qkv,*p_t,*p_p,*p_ff,*p_at,*p_wt,*p_b3;
    if (!p_h) {
        void* p;
        cudaGetSymbolAddress(&p, g_h);   p_h   = (float*)p;
        cudaGetSymbolAddress(&p, g_qkv); p_qkv = (float*)p;
        cudaGetSymbolAddress(&p, g_t);   p_t   = (float*)p;
        cudaGetSymbolAddress(&p, g_p);   p_p   = (float*)p;
        cudaGetSymbolAddress(&p, g_ff);  p_ff  = (float*)p;
        cudaGetSymbolAddress(&p, g_at);  p_at  = (float*)p;
        cudaGetSymbolAddress(&p, g_wt);  p_wt  = (float*)p;
        cudaGetSymbolAddress(&p, g_b3);  p_b3  = (float*)p;
        cudaFuncSetAttribute(gemm_tf32_kernel,
            cudaFuncAttributeMaxDynamicSharedMemorySize, GEMM_SMEM);
        cudaFuncSetAttribute(attn_scores_gemm,
            cudaFuncAttributeMaxDynamicSharedMemorySize, SCORES_SMEM);
        cudaFuncSetAttribute(attn_o_mma_kernel,
            cudaFuncAttributeMaxDynamicSharedMemorySize, ATTN_SMEM);
    }

    embed_kernel<<<(MM*DD + 255)/256, 256>>>(x, emb, pe);

    const int wblk = (DD*DD/4 + 255)/256;

    for (int l = 0; l < LL; l++) {
        const float* wq_l = wq + (size_t)l*DD*DD;
        const float* wk_l = wk + (size_t)l*DD*DD;
        const float* wv_l = wv + (size_t)l*DD*DD;
        const float* wo_l = wo + (size_t)l*DD*DD;
        const float* w1_l = w1 + (size_t)l*DD*DFF;
        const float* w2_l = w2 + (size_t)l*DFF*DD;

        // ---- fused QKV ----
        cvt(p_h, p_at, (size_t)MM*DD);
        cvt_tf32_cols_kernel<<<wblk, 256>>>(wq_l, p_wt, DD, DD, QSTR, 0);
        cvt_tf32_cols_kernel<<<wblk, 256>>>(wk_l, p_wt, DD, DD, QSTR, DD);
        cvt_tf32_cols_kernel<<<wblk, 256>>>(wv_l, p_wt, DD, DD, QSTR, 2*DD);
        concat3_kernel<<<(QSTR+255)/256, 256>>>(bq + l*DD, bk + l*DD, bv + l*DD, p_b3);
        dim3 gqkv(MM/128, QSTR/128);
        gemm_tf32_kernel<<<gqkv, 256, GEMM_SMEM>>>(p_at, p_wt, p_b3, p_qkv, DD, QSTR, 0);

        // ---- attention ----
        float* amap_l = out + LOGITS_ELEMS + (size_t)l*AMAP_ELEMS;
        dim3 gsc(36, BB*HH);
        attn_scores_gemm<<<gsc, 256, SCORES_SMEM>>>(p_qkv, amap_l);
        dim3 gsm(SS, BB*HH);
        softmax_rows<<<gsm, 256>>>(amap_l);
        dim3 gao(SS/128, BB*HH);
        attn_o_mma_kernel<<<gao, 256, ATTN_SMEM>>>(amap_l, p_qkv, p_t);

        // ---- output projection ----
        cvt(p_t, p_at, (size_t)MM*DD);
        cvt(wo_l, p_wt, (size_t)DD*DD);
        dim3 gproj(MM/128, DD/128);
        gemm_tf32_kernel<<<gproj, 256, GEMM_SMEM>>>(p_at, p_wt, bo + l*DD, p_p, DD, DD, 0);
        add_ln_kernel<<<MM, 256>>>(p_h, p_p, g1 + l*DD, be1 + l*DD, p_h);

        // ---- FFN ----
        cvt(p_h, p_at, (size_t)MM*DD);
        cvt(w1_l, p_wt, (size_t)DD*DFF);
        dim3 gff1(MM/128, DFF/128);
        gemm_tf32_kernel<<<gff1, 256, GEMM_SMEM>>>(p_at, p_wt, b1 + l*DFF, p_ff, DD, DFF, 1);
        cvt(p_ff, p_at, (size_t)MM*DFF);
        cvt(w2_l, p_wt, (size_t)DFF*DD);
        dim3 gff2(MM/128, DD/128);
        gemm_tf32_kernel<<<gff2, 256, GEMM_SMEM>>>(p_at, p_wt, b2 + l*DD, p_t, DFF, DD, 0);
        add_ln_kernel<<<MM, 256>>>(p_h, p_t, g2 + l*DD, be2 + l*DD, p_h);
    }

    // ---- logits ----
    cvt(p_h, p_at, (size_t)MM*DD);
    cvt(wout, p_wt, (size_t)DD*VV);
    dim3 glog(MM/128, VV/128);
    gemm_tf32_kernel<<<glog, 256, GEMM_SMEM>>>(p_at, p_wt, bout, out, DD, VV, 0);
}